// round 10
// baseline (speedup 1.0000x reference)
#include <cuda_runtime.h>
#include <cuda_bf16.h>
#include <math.h>
#include <stdint.h>

#define Nn 50000
#define Ee 300000
#define Mm (Ee + Nn)
#define NPAD 50048          // Nn rounded up to 128
#define IND 64
#define Hh 256
#define Ll 4
#define NBc 181
#define Gg 64
#define SCANB 1024
#define NSCANB ((Nn + SCANB - 1) / SCANB)

// weight split offsets (elements)
#define WOFF_IN  0
#define WOFF_L   16384
#define WOFF_R   (16384 + 262144)
#define WOFF_G1  (16384 + 524288)
#define WTOT     (16384 + 524288 + 65536)

// ---------------- scratch (device globals; no allocation allowed) ----------------
__device__ float g_x[Nn * Hh];
__device__ float g_xl[Nn * Hh];
__device__ float g_xr[Nn * Hh];
__device__ __align__(16) __nv_bfloat16 g_xhi[NPAD * Hh];
__device__ __align__(16) __nv_bfloat16 g_xlo[NPAD * Hh];
__device__ __align__(16) __nv_bfloat16 g_xinhi[NPAD * IND];
__device__ __align__(16) __nv_bfloat16 g_xinlo[NPAD * IND];
__device__ __align__(16) __nv_bfloat16 g_whi[WTOT];
__device__ __align__(16) __nv_bfloat16 g_wlo[WTOT];
__device__ float g_gate[Nn];
__device__ float g_pooled[Gg * Hh];
__device__ int   g_src[Mm];
__device__ int   g_dst[Mm];
__device__ int   g_deg[Nn];
__device__ int   g_incl[Nn];
__device__ int   g_bsum[NSCANB];
__device__ int   g_rowptr[Nn + 1];
__device__ int   g_cursor[Nn];
__device__ int   g_csrsrc[Mm];
__device__ int   g_bstart[Gg + 1];
__device__ int   g_idx64;

// ---------------- helpers ----------------
__device__ __forceinline__ uint32_t smem_to_u32(const void* smem_ptr) {
    uint32_t addr;
    asm("{ .reg .u64 tmp; cvta.to.shared.u64 tmp, %1; cvt.u32.u64 %0, tmp; }"
        : "=r"(addr) : "l"(smem_ptr));
    return addr;
}

__device__ __forceinline__ void cpa16(uint32_t dst, const void* src) {
    asm volatile("cp.async.cg.shared.global [%0], [%1], 16;" :: "r"(dst), "l"(src));
}

__device__ __forceinline__ void split2(float x, float y, uint32_t& hi, uint32_t& lo) {
    __nv_bfloat16 hx = __float2bfloat16_rn(x);
    __nv_bfloat16 hy = __float2bfloat16_rn(y);
    __nv_bfloat16 lx = __float2bfloat16_rn(x - __bfloat162float(hx));
    __nv_bfloat16 ly = __float2bfloat16_rn(y - __bfloat162float(hy));
    hi = ((uint32_t)__bfloat16_as_ushort(hy) << 16) | __bfloat16_as_ushort(hx);
    lo = ((uint32_t)__bfloat16_as_ushort(ly) << 16) | __bfloat16_as_ushort(lx);
}

__device__ __forceinline__ void mma16816(float* c, uint32_t a0, uint32_t a1, uint32_t a2, uint32_t a3,
                                         uint32_t b0, uint32_t b1) {
    asm volatile(
        "mma.sync.aligned.m16n8k16.row.col.f32.bf16.bf16.f32 "
        "{%0,%1,%2,%3}, {%4,%5,%6,%7}, {%8,%9}, {%0,%1,%2,%3};"
        : "+f"(c[0]), "+f"(c[1]), "+f"(c[2]), "+f"(c[3])
        : "r"(a0), "r"(a1), "r"(a2), "r"(a3), "r"(b0), "r"(b1));
}

// ---------------- split kernels ----------------
__global__ void split_pairs_kernel(const float2* __restrict__ src,
                                   uint32_t* __restrict__ dhi, uint32_t* __restrict__ dlo, int n2) {
    int i = blockIdx.x * blockDim.x + threadIdx.x;
    if (i >= n2) return;
    float2 v = src[i];
    uint32_t h, l;
    split2(v.x, v.y, h, l);
    dhi[i] = h; dlo[i] = l;
}

// x_in split with zero pad to NPAD rows
__global__ void split_xin_kernel(const float2* __restrict__ src,
                                 uint32_t* __restrict__ dhi, uint32_t* __restrict__ dlo) {
    int i = blockIdx.x * blockDim.x + threadIdx.x;
    if (i >= NPAD * (IND / 2)) return;
    float2 v = (i < Nn * (IND / 2)) ? src[i] : make_float2(0.f, 0.f);
    uint32_t h, l;
    split2(v.x, v.y, h, l);
    dhi[i] = h; dlo[i] = l;
}

// ---------------- bf16 pipelined tensor GEMM ----------------
// C[n,256] = A[n,K] @ W[256,K]^T + bias; A,W pre-split bf16 hi/lo.
// CTA 128x128, 8 warps (4x2), warp tile 32x64, K-chunk 32, 2-stage cp.async.
#define RS2 80
#define ST_AHI 0
#define ST_ALO 10240
#define ST_BHI 20480
#define ST_BLO 30720
#define ST_SZ  40960
#define GSM_TOT (2 * ST_SZ)

__global__ __launch_bounds__(256, 2)
void gemm_bf16_kernel(const __nv_bfloat16* __restrict__ Ahi, const __nv_bfloat16* __restrict__ Alo,
                      const __nv_bfloat16* __restrict__ Bhi, const __nv_bfloat16* __restrict__ Blo,
                      const float* __restrict__ bias, float* __restrict__ C,
                      uint32_t* __restrict__ Chi, uint32_t* __restrict__ Clo, int wsplit,
                      int n, int K, int relu) {
    extern __shared__ char smc[];
    uint32_t sb = smem_to_u32(smc);
    const int tid = threadIdx.x;
    const int wid = tid >> 5, lane = tid & 31;
    const int row0 = blockIdx.y * 128;
    const int col0 = blockIdx.x * 128;
    const int wr = (wid & 3) * 32;
    const int wc = (wid >> 2) * 64;
    const int lr = lane >> 2;
    const int lq = lane & 3;

    float acc[16][4];
#pragma unroll
    for (int t = 0; t < 16; t++)
#pragma unroll
        for (int q = 0; q < 4; q++) acc[t][q] = 0.f;

    const int nc = K >> 5;

    auto issue = [&](int kc, int stage) {
        const int kOff = kc * 32;
        const uint32_t s0 = sb + stage * ST_SZ;
#pragma unroll
        for (int it = 0; it < 2; it++) {
            int i = tid + it * 256;      // 0..511
            int r = i >> 2, pc = i & 3;
            uint32_t d = (uint32_t)(r * RS2 + pc * 16);
            size_t aoff = (size_t)(row0 + r) * K + kOff + pc * 8;
            cpa16(s0 + ST_AHI + d, Ahi + aoff);
            cpa16(s0 + ST_ALO + d, Alo + aoff);
            size_t boff = (size_t)(col0 + r) * K + kOff + pc * 8;
            cpa16(s0 + ST_BHI + d, Bhi + boff);
            cpa16(s0 + ST_BLO + d, Blo + boff);
        }
    };

    issue(0, 0);
    asm volatile("cp.async.commit_group;" ::: "memory");

    for (int kc = 0; kc < nc; kc++) {
        if (kc + 1 < nc) issue(kc + 1, (kc + 1) & 1);
        asm volatile("cp.async.commit_group;" ::: "memory");
        asm volatile("cp.async.wait_group 1;" ::: "memory");
        __syncthreads();
        char* st = smc + (kc & 1) * ST_SZ;
#pragma unroll
        for (int ks = 0; ks < 2; ks++) {
            const int kb = (ks * 16 + lq * 2) * 2;
            uint32_t ah[2][4], al[2][4];
#pragma unroll
            for (int mt = 0; mt < 2; mt++) {
                char* pa = st + (wr + mt * 16 + lr) * RS2 + kb;
                ah[mt][0] = *(const uint32_t*)(pa + ST_AHI);
                ah[mt][1] = *(const uint32_t*)(pa + ST_AHI + 8 * RS2);
                ah[mt][2] = *(const uint32_t*)(pa + ST_AHI + 16);
                ah[mt][3] = *(const uint32_t*)(pa + ST_AHI + 8 * RS2 + 16);
                al[mt][0] = *(const uint32_t*)(pa + ST_ALO);
                al[mt][1] = *(const uint32_t*)(pa + ST_ALO + 8 * RS2);
                al[mt][2] = *(const uint32_t*)(pa + ST_ALO + 16);
                al[mt][3] = *(const uint32_t*)(pa + ST_ALO + 8 * RS2 + 16);
            }
#pragma unroll
            for (int nt = 0; nt < 8; nt++) {
                char* pb = st + (wc + nt * 8 + lr) * RS2 + kb;
                uint32_t bh0 = *(const uint32_t*)(pb + ST_BHI);
                uint32_t bh1 = *(const uint32_t*)(pb + ST_BHI + 16);
                uint32_t bl0 = *(const uint32_t*)(pb + ST_BLO);
                uint32_t bl1 = *(const uint32_t*)(pb + ST_BLO + 16);
#pragma unroll
                for (int mt = 0; mt < 2; mt++) {
                    float* c = acc[mt * 8 + nt];
                    mma16816(c, ah[mt][0], ah[mt][1], ah[mt][2], ah[mt][3], bh0, bh1);
                    mma16816(c, ah[mt][0], ah[mt][1], ah[mt][2], ah[mt][3], bl0, bl1);
                    mma16816(c, al[mt][0], al[mt][1], al[mt][2], al[mt][3], bh0, bh1);
                }
            }
        }
        __syncthreads();
    }

    // ---- epilogue ----
#pragma unroll
    for (int mt = 0; mt < 2; mt++) {
#pragma unroll
        for (int nt = 0; nt < 8; nt++) {
            const float* c = acc[mt * 8 + nt];
            int col = col0 + wc + nt * 8 + lq * 2;
            float b0 = bias[col], b1 = bias[col + 1];
            int r0 = row0 + wr + mt * 16 + lr;
            int r1 = r0 + 8;
            float2 o;
            uint32_t h, l;
            if (r0 < n) {
                o.x = c[0] + b0; o.y = c[1] + b1;
                if (relu) { o.x = fmaxf(o.x, 0.f); o.y = fmaxf(o.y, 0.f); }
                *(float2*)&C[(size_t)r0 * Hh + col] = o;
                if (wsplit) {
                    split2(o.x, o.y, h, l);
                    Chi[(size_t)r0 * 128 + (col >> 1)] = h;
                    Clo[(size_t)r0 * 128 + (col >> 1)] = l;
                }
            }
            if (r1 < n) {
                o.x = c[2] + b0; o.y = c[3] + b1;
                if (relu) { o.x = fmaxf(o.x, 0.f); o.y = fmaxf(o.y, 0.f); }
                *(float2*)&C[(size_t)r1 * Hh + col] = o;
                if (wsplit) {
                    split2(o.x, o.y, h, l);
                    Chi[(size_t)r1 * 128 + (col >> 1)] = h;
                    Clo[(size_t)r1 * 128 + (col >> 1)] = l;
                }
            }
        }
    }
}

// ---------------- index width detection ----------------
__global__ void detect_kernel(const void* ei) {
    const long long* p = (const long long*)ei;
    int ok = 1;
    for (int i = 0; i < 64; i++) {
        long long v = p[i];
        if (v < 0 || v >= Nn) { ok = 0; break; }
    }
    g_idx64 = ok;
}

__global__ void zero_deg_kernel() {
    int i = blockIdx.x * blockDim.x + threadIdx.x;
    if (i < Nn) g_deg[i] = 0;
}

__global__ void convert_count_kernel(const void* ei) {
    int m = blockIdx.x * blockDim.x + threadIdx.x;
    if (m >= Mm) return;
    int is64 = g_idx64;
    int s, d;
    if (m < Ee) {
        if (is64) { s = (int)((const long long*)ei)[m]; d = (int)((const long long*)ei)[(long long)Ee + m]; }
        else      { s = ((const int*)ei)[m];            d = ((const int*)ei)[Ee + m]; }
    } else { s = d = m - Ee; }
    g_src[m] = s;
    g_dst[m] = d;
    atomicAdd(&g_deg[d], 1);
}

__global__ void scan1_kernel() {
    __shared__ int smi[SCANB];
    int i = blockIdx.x * SCANB + threadIdx.x;
    int v = (i < Nn) ? g_deg[i] : 0;
    smi[threadIdx.x] = v;
    __syncthreads();
    for (int o = 1; o < SCANB; o <<= 1) {
        int t = (threadIdx.x >= o) ? smi[threadIdx.x - o] : 0;
        __syncthreads();
        smi[threadIdx.x] += t;
        __syncthreads();
    }
    if (i < Nn) g_incl[i] = smi[threadIdx.x];
    if (threadIdx.x == SCANB - 1) g_bsum[blockIdx.x] = smi[SCANB - 1];
}

__global__ void scan2_kernel() {
    __shared__ int smi[64];
    int t = threadIdx.x;
    int v = (t < NSCANB) ? g_bsum[t] : 0;
    smi[t] = v;
    __syncthreads();
    for (int o = 1; o < 64; o <<= 1) {
        int u = (t >= o) ? smi[t - o] : 0;
        __syncthreads();
        smi[t] += u;
        __syncthreads();
    }
    if (t < NSCANB) g_bsum[t] = smi[t];
}

__global__ void scan3_kernel() {
    int i = blockIdx.x * blockDim.x + threadIdx.x;
    if (i >= Nn) return;
    int b = i >> 10;
    int excl = g_incl[i] - g_deg[i] + (b ? g_bsum[b - 1] : 0);
    g_rowptr[i] = excl;
    g_cursor[i] = excl;
    if (i == 0) g_rowptr[Nn] = Mm;
}

__global__ void csr_fill_kernel() {
    int m = blockIdx.x * blockDim.x + threadIdx.x;
    if (m >= Mm) return;
    int d = g_dst[m];
    int pos = atomicAdd(&g_cursor[d], 1);
    g_csrsrc[pos] = g_src[m];
}

// ---------------- fused edge phase (warp/dst): online softmax + LN + residual + split out
__global__ __launch_bounds__(256)
void edge_fused_kernel(const int* __restrict__ rowptr, const int* __restrict__ csrsrc,
                       const float4* __restrict__ xl, const float4* __restrict__ xr,
                       const float4* __restrict__ att4,
                       const float4* __restrict__ bias_c4,
                       const float4* __restrict__ lg4, const float4* __restrict__ lb4,
                       float4* __restrict__ x,
                       uint32_t* __restrict__ xhi32, uint32_t* __restrict__ xlo32) {
    int d = (blockIdx.x * blockDim.x + threadIdx.x) >> 5;
    int lane = threadIdx.x & 31;
    if (d >= Nn) return;

    float4 r0 = xr[(size_t)d * 64 + lane];
    float4 r1 = xr[(size_t)d * 64 + 32 + lane];
    float4 t0 = att4[lane];
    float4 t1 = att4[32 + lane];

    float m = -INFINITY, s = 0.f;
    float4 acc0 = make_float4(0,0,0,0), acc1 = make_float4(0,0,0,0);

    int p0 = rowptr[d], p1 = rowptr[d + 1];
    int src = csrsrc[p0];
    float4 l0 = xl[(size_t)src * 64 + lane];
    float4 l1 = xl[(size_t)src * 64 + 32 + lane];
    for (int p = p0; p < p1; p++) {
        float4 c0 = l0, c1 = l1;
        if (p + 1 < p1) {                       // prefetch next row before reduce chain
            int s2 = csrsrc[p + 1];
            l0 = xl[(size_t)s2 * 64 + lane];
            l1 = xl[(size_t)s2 * 64 + 32 + lane];
        }
        float e = 0.f, v;
        v = c0.x + r0.x; v = (v > 0.f) ? v : 0.2f * v; e = fmaf(v, t0.x, e);
        v = c0.y + r0.y; v = (v > 0.f) ? v : 0.2f * v; e = fmaf(v, t0.y, e);
        v = c0.z + r0.z; v = (v > 0.f) ? v : 0.2f * v; e = fmaf(v, t0.z, e);
        v = c0.w + r0.w; v = (v > 0.f) ? v : 0.2f * v; e = fmaf(v, t0.w, e);
        v = c1.x + r1.x; v = (v > 0.f) ? v : 0.2f * v; e = fmaf(v, t1.x, e);
        v = c1.y + r1.y; v = (v > 0.f) ? v : 0.2f * v; e = fmaf(v, t1.y, e);
        v = c1.z + r1.z; v = (v > 0.f) ? v : 0.2f * v; e = fmaf(v, t1.z, e);
        v = c1.w + r1.w; v = (v > 0.f) ? v : 0.2f * v; e = fmaf(v, t1.w, e);
#pragma unroll
        for (int o = 16; o; o >>= 1) e += __shfl_xor_sync(0xffffffffu, e, o);
        if (e <= m) {                            // common case: no accumulator rescale
            float w = __expf(e - m);
            s += w;
            acc0.x += w * c0.x; acc0.y += w * c0.y; acc0.z += w * c0.z; acc0.w += w * c0.w;
            acc1.x += w * c1.x; acc1.y += w * c1.y; acc1.z += w * c1.z; acc1.w += w * c1.w;
        } else {
            float cc = __expf(m - e);            // first iter: exp(-inf)=0
            s = s * cc + 1.f;
            acc0.x = acc0.x * cc + c0.x; acc0.y = acc0.y * cc + c0.y;
            acc0.z = acc0.z * cc + c0.z; acc0.w = acc0.w * cc + c0.w;
            acc1.x = acc1.x * cc + c1.x; acc1.y = acc1.y * cc + c1.y;
            acc1.z = acc1.z * cc + c1.z; acc1.w = acc1.w * cc + c1.w;
            m = e;
        }
    }
    float inv = 1.f / s;
    float4 bc0 = bias_c4[lane], bc1 = bias_c4[32 + lane];
    float v0x = acc0.x * inv + bc0.x, v0y = acc0.y * inv + bc0.y;
    float v0z = acc0.z * inv + bc0.z, v0w = acc0.w * inv + bc0.w;
    float v1x = acc1.x * inv + bc1.x, v1y = acc1.y * inv + bc1.y;
    float v1z = acc1.z * inv + bc1.z, v1w = acc1.w * inv + bc1.w;

    float sum = v0x + v0y + v0z + v0w + v1x + v1y + v1z + v1w;
#pragma unroll
    for (int o = 16; o; o >>= 1) sum += __shfl_xor_sync(0xffffffffu, sum, o);
    float mu = sum * (1.f / Hh);
    float d0x = v0x - mu, d0y = v0y - mu, d0z = v0z - mu, d0w = v0w - mu;
    float d1x = v1x - mu, d1y = v1y - mu, d1z = v1z - mu, d1w = v1w - mu;
    float vsum = d0x*d0x + d0y*d0y + d0z*d0z + d0w*d0w + d1x*d1x + d1y*d1y + d1z*d1z + d1w*d1w;
#pragma unroll
    for (int o = 16; o; o >>= 1) vsum += __shfl_xor_sync(0xffffffffu, vsum, o);
    float rs = rsqrtf(vsum * (1.f / Hh) + 1e-5f);

    float4 lg0 = lg4[lane], lg1 = lg4[32 + lane];
    float4 lb0 = lb4[lane], lb1 = lb4[32 + lane];
    float4 xr0 = x[(size_t)d * 64 + lane];
    float4 xr1 = x[(size_t)d * 64 + 32 + lane];
    float4 o0, o1;
    o0.x = fmaxf(d0x * rs * lg0.x + lb0.x, 0.f) + xr0.x;
    o0.y = fmaxf(d0y * rs * lg0.y + lb0.y, 0.f) + xr0.y;
    o0.z = fmaxf(d0z * rs * lg0.z + lb0.z, 0.f) + xr0.z;
    o0.w = fmaxf(d0w * rs * lg0.w + lb0.w, 0.f) + xr0.w;
    o1.x = fmaxf(d1x * rs * lg1.x + lb1.x, 0.f) + xr1.x;
    o1.y = fmaxf(d1y * rs * lg1.y + lb1.y, 0.f) + xr1.y;
    o1.z = fmaxf(d1z * rs * lg1.z + lb1.z, 0.f) + xr1.z;
    o1.w = fmaxf(d1w * rs * lg1.w + lb1.w, 0.f) + xr1.w;
    x[(size_t)d * 64 + lane] = o0;
    x[(size_t)d * 64 + 32 + lane] = o1;

    // bf16 hi/lo split for next layer's GEMM A operand
    size_t b32 = (size_t)d * 128 + 2 * lane;
    uint32_t h, l;
    split2(o0.x, o0.y, h, l); xhi32[b32]      = h; xlo32[b32]      = l;
    split2(o0.z, o0.w, h, l); xhi32[b32 + 1]  = h; xlo32[b32 + 1]  = l;
    split2(o1.x, o1.y, h, l); xhi32[b32 + 64] = h; xlo32[b32 + 64] = l;
    split2(o1.z, o1.w, h, l); xhi32[b32 + 65] = h; xlo32[b32 + 65] = l;
}

// ---------------- gate dot ----------------
__global__ void gate_dot_kernel(const float4* __restrict__ hid, const float4* __restrict__ Wg2,
                                const float* __restrict__ bg2, float* __restrict__ gate) {
    int w = (blockIdx.x * blockDim.x + threadIdx.x) >> 5;
    int lane = threadIdx.x & 31;
    if (w >= Nn) return;
    const float4* p = hid + (size_t)w * 64;
    float sum = 0.f;
#pragma unroll
    for (int j = lane; j < 64; j += 32) {
        float4 a = p[j], t = Wg2[j];
        sum = fmaf(a.x, t.x, fmaf(a.y, t.y, fmaf(a.z, t.z, fmaf(a.w, t.w, sum))));
    }
#pragma unroll
    for (int o = 16; o; o >>= 1) sum += __shfl_xor_sync(0xffffffffu, sum, o);
    if (lane == 0) gate[w] = sum + bg2[0];
}

// ---------------- batch segment boundaries ----------------
__global__ void bstart_kernel(const void* __restrict__ batch) {
    int g = threadIdx.x;
    if (g > Gg) return;
    if (g == Gg) { g_bstart[Gg] = Nn; return; }
    int is64 = g_idx64;
    int lo = 0, hi = Nn;
    while (lo < hi) {
        int mid = (lo + hi) >> 1;
        long long v = is64 ? ((const long long*)batch)[mid] : (long long)((const int*)batch)[mid];
        if (v < g) lo = mid + 1; else hi = mid;
    }
    g_bstart[g] = lo;
}

// ---------------- segmented softmax pooling ----------------
__global__ __launch_bounds__(256)
void segpool_kernel(const float* __restrict__ gate, const float* __restrict__ x,
                    float* __restrict__ pooled) {
    int g = blockIdx.x, tid = threadIdx.x;
    int s = g_bstart[g], e = g_bstart[g + 1];
    __shared__ float red[8];
    __shared__ float ws[256];
    if (s >= e) { pooled[(size_t)g * Hh + tid] = 0.f; return; }

    float m = -INFINITY;
    for (int i = s + tid; i < e; i += 256) m = fmaxf(m, gate[i]);
#pragma unroll
    for (int o = 16; o; o >>= 1) m = fmaxf(m, __shfl_xor_sync(0xffffffffu, m, o));
    if ((tid & 31) == 0) red[tid >> 5] = m;
    __syncthreads();
    m = fmaxf(fmaxf(fmaxf(red[0], red[1]), fmaxf(red[2], red[3])),
              fmaxf(fmaxf(red[4], red[5]), fmaxf(red[6], red[7])));
    __syncthreads();

    float sum = 0.f;
    for (int i = s + tid; i < e; i += 256) sum += __expf(gate[i] - m);
#pragma unroll
    for (int o = 16; o; o >>= 1) sum += __shfl_xor_sync(0xffffffffu, sum, o);
    if ((tid & 31) == 0) red[tid >> 5] = sum;
    __syncthreads();
    sum = red[0] + red[1] + red[2] + red[3] + red[4] + red[5] + red[6] + red[7];
    __syncthreads();

    float acc = 0.f;
    for (int i0 = s; i0 < e; i0 += 256) {
        int n = min(256, e - i0);
        if (tid < n) ws[tid] = __expf(gate[i0 + tid] - m);
        __syncthreads();
        for (int j = 0; j < n; j++) acc = fmaf(ws[j], x[(size_t)(i0 + j) * Hh + tid], acc);
        __syncthreads();
    }
    pooled[(size_t)g * Hh + tid] = acc / sum;
}

// ---------------- head ----------------
__global__ void head_kernel(const float* __restrict__ pooled,
                            const float* __restrict__ Ws, const float* __restrict__ bs,
                            const float* __restrict__ Wc, const float* __restrict__ bc,
                            const float* __restrict__ Wr1, const float* __restrict__ br1,
                            const float* __restrict__ Wr2, const float* __restrict__ br2,
                            float* __restrict__ out) {
    int g = blockIdx.x, t = threadIdx.x;
    __shared__ float sp[Hh];
    __shared__ float sz[Hh];
    __shared__ float sr[128];
    sp[t] = pooled[(size_t)g * Hh + t];
    __syncthreads();
    float acc = bs[t];
#pragma unroll 8
    for (int k = 0; k < Hh; k++) acc = fmaf(sp[k], Ws[(size_t)t * Hh + k], acc);
    sz[t] = fmaxf(acc, 0.f);
    __syncthreads();
    if (t < NBc) {
        float a2 = bc[t];
#pragma unroll 8
        for (int k = 0; k < Hh; k++) a2 = fmaf(sz[k], Wc[(size_t)t * Hh + k], a2);
        out[(size_t)g * NBc + t] = a2;
    }
    if (t < 128) {
        float a3 = br1[t];
#pragma unroll 8
        for (int k = 0; k < Hh; k++) a3 = fmaf(sz[k], Wr1[(size_t)t * Hh + k], a3);
        sr[t] = fmaxf(a3, 0.f);
    }
    __syncthreads();
    if (t < 128) {
        float v = sr[t] * Wr2[t];
#pragma unroll
        for (int o = 16; o; o >>= 1) v += __shfl_xor_sync(0xffffffffu, v, o);
        if ((t & 31) == 0) sp[t >> 5] = v;
    }
    __syncthreads();
    if (t == 0) {
        float tot = sp[0] + sp[1] + sp[2] + sp[3] + br2[0];
        out[(size_t)Gg * NBc + g] = tanhf(tot);
    }
}

// ---------------- launch ----------------
extern "C" void kernel_launch(void* const* d_in, const int* in_sizes, int n_in,
                              void* d_out, int out_size) {
    const float* x_in   = (const float*)d_in[0];
    const void*  ei     = d_in[1];
    const void*  batch  = d_in[2];
    const float* W_in   = (const float*)d_in[3];
    const float* b_in   = (const float*)d_in[4];
    const float* Wl     = (const float*)d_in[5];
    const float* bl     = (const float*)d_in[6];
    const float* Wr     = (const float*)d_in[7];
    const float* br     = (const float*)d_in[8];
    const float* att    = (const float*)d_in[9];
    const float* bias_c = (const float*)d_in[10];
    const float* ln_g   = (const float*)d_in[11];
    const float* ln_b   = (const float*)d_in[12];
    const float* Wg1    = (const float*)d_in[13];
    const float* bg1    = (const float*)d_in[14];
    const float* Wg2    = (const float*)d_in[15];
    const float* bg2    = (const float*)d_in[16];
    const float* Ws     = (const float*)d_in[17];
    const float* bs     = (const float*)d_in[18];
    const float* Wc     = (const float*)d_in[19];
    const float* bc     = (const float*)d_in[20];
    const float* Wr1    = (const float*)d_in[21];
    const float* br1    = (const float*)d_in[22];
    const float* Wr2    = (const float*)d_in[23];
    const float* br2    = (const float*)d_in[24];
    float* out = (float*)d_out;

    float *px, *pxl, *pxr, *pgate, *ppooled;
    __nv_bfloat16 *pxhi, *pxlo, *pxinhi, *pxinlo, *pwhi, *pwlo;
    int *prowptr, *pcsrsrc;
    cudaGetSymbolAddress((void**)&px,      g_x);
    cudaGetSymbolAddress((void**)&pxl,     g_xl);
    cudaGetSymbolAddress((void**)&pxr,     g_xr);
    cudaGetSymbolAddress((void**)&pxhi,    g_xhi);
    cudaGetSymbolAddress((void**)&pxlo,    g_xlo);
    cudaGetSymbolAddress((void**)&pxinhi,  g_xinhi);
    cudaGetSymbolAddress((void**)&pxinlo,  g_xinlo);
    cudaGetSymbolAddress((void**)&pwhi,    g_whi);
    cudaGetSymbolAddress((void**)&pwlo,    g_wlo);
    cudaGetSymbolAddress((void**)&pgate,   g_gate);
    cudaGetSymbolAddress((void**)&ppooled, g_pooled);
    cudaGetSymbolAddress((void**)&prowptr, g_rowptr);
    cudaGetSymbolAddress((void**)&pcsrsrc, g_csrsrc);

    cudaFuncSetAttribute(gemm_bf16_kernel, cudaFuncAttributeMaxDynamicSharedMemorySize, GSM_TOT);

    const dim3 gemm_grid(2, (Nn + 127) / 128);
    const int NODE_W_BLOCKS = (Nn * 32 + 255) / 256;

    // ---- weight + input splits ----
    split_pairs_kernel<<<(16384/2 + 255)/256, 256>>>((const float2*)W_in,
        (uint32_t*)(pwhi + WOFF_IN), (uint32_t*)(pwlo + WOFF_IN), 16384/2);
    split_pairs_kernel<<<(262144/2 + 255)/256, 256>>>((const float2*)Wl,
        (uint32_t*)(pwhi + WOFF_L), (uint32_t*)(pwlo + WOFF_L), 262144/2);
    split_pairs_kernel<<<(262144/2 + 255)/256, 256>>>((const float2*)Wr,
        (uint32_t*)(pwhi + WOFF_R), (uint32_t*)(pwlo + WOFF_R), 262144/2);
    split_pairs_kernel<<<(65536/2 + 255)/256, 256>>>((const float2*)Wg1,
        (uint32_t*)(pwhi + WOFF_G1), (uint32_t*)(pwlo + WOFF_G1), 65536/2);
    split_xin_kernel<<<(NPAD*(IND/2) + 255)/256, 256>>>((const float2*)x_in,
        (uint32_t*)pxinhi, (uint32_t*)pxinlo);

    // ---- CSR build ----
    detect_kernel<<<1, 1>>>(ei);
    zero_deg_kernel<<<(Nn + 255) / 256, 256>>>();
    convert_count_kernel<<<(Mm + 255) / 256, 256>>>(ei);
    scan1_kernel<<<NSCANB, SCANB>>>();
    scan2_kernel<<<1, 64>>>();
    scan3_kernel<<<(Nn + 255) / 256, 256>>>();
    csr_fill_kernel<<<(Mm + 255) / 256, 256>>>();
    bstart_kernel<<<1, Gg + 1>>>(batch);

    // ---- input projection (K=64): writes px fp32 AND split for layer-0 GEMMs ----
    gemm_bf16_kernel<<<gemm_grid, 256, GSM_TOT>>>(pxinhi, pxinlo,
        pwhi + WOFF_IN, pwlo + WOFF_IN, b_in, px,
        (uint32_t*)pxhi, (uint32_t*)pxlo, 1, Nn, IND, 0);

    // ---- GAT layers ----
    for (int l = 0; l < Ll; l++) {
        gemm_bf16_kernel<<<gemm_grid, 256, GSM_TOT>>>(pxhi, pxlo,
            pwhi + WOFF_L + (size_t)l * Hh * Hh, pwlo + WOFF_L + (size_t)l * Hh * Hh,
            bl + l * Hh, pxl, nullptr, nullptr, 0, Nn, Hh, 0);
        gemm_bf16_kernel<<<gemm_grid, 256, GSM_TOT>>>(pxhi, pxlo,
            pwhi + WOFF_R + (size_t)l * Hh * Hh, pwlo + WOFF_R + (size_t)l * Hh * Hh,
            br + l * Hh, pxr, nullptr, nullptr, 0, Nn, Hh, 0);
        edge_fused_kernel<<<NODE_W_BLOCKS, 256>>>(prowptr, pcsrsrc,
            (const float4*)pxl, (const float4*)pxr,
            (const float4*)(att + l * Hh),
            (const float4*)(bias_c + l * Hh),
            (const float4*)(ln_g + l * Hh), (const float4*)(ln_b + l * Hh),
            (float4*)px, (uint32_t*)pxhi, (uint32_t*)pxlo);
    }

    // ---- readout ----
    gemm_bf16_kernel<<<gemm_grid, 256, GSM_TOT>>>(pxhi, pxlo,
        pwhi + WOFF_G1, pwlo + WOFF_G1, bg1, pxl, nullptr, nullptr, 0, Nn, Hh, 1);
    gate_dot_kernel<<<NODE_W_BLOCKS, 256>>>((const float4*)pxl, (const float4*)Wg2, bg2, pgate);
    segpool_kernel<<<Gg, 256>>>(pgate, px, ppooled);
    head_kernel<<<Gg, Hh>>>(ppooled, Ws, bs, Wc, bc, Wr1, br1, Wr2, br2, out);
}

// round 14
// speedup vs baseline: 1.0602x; 1.0602x over previous
#include <cuda_runtime.h>
#include <cuda_bf16.h>
#include <math.h>
#include <stdint.h>

#define Nn 50000
#define Ee 300000
#define Mm (Ee + Nn)
#define NPAD 50048          // Nn rounded up to 128
#define IND 64
#define Hh 256
#define Ll 4
#define NBc 181
#define Gg 64
#define SCANB 1024
#define NSCANB ((Nn + SCANB - 1) / SCANB)

// weight split offsets (elements)
#define WOFF_IN  0
#define WOFF_L   16384
#define WOFF_R   (16384 + 262144)
#define WOFF_G1  (16384 + 524288)
#define WTOT     (16384 + 524288 + 65536)

// ---------------- scratch (device globals; no allocation allowed) ----------------
__device__ float g_x[Nn * Hh];
__device__ float g_xl[Nn * Hh];
__device__ float g_xr[Nn * Hh];
__device__ __align__(16) __nv_bfloat16 g_xhi[NPAD * Hh];
__device__ __align__(16) __nv_bfloat16 g_xlo[NPAD * Hh];
__device__ __align__(16) __nv_bfloat16 g_xinhi[NPAD * IND];
__device__ __align__(16) __nv_bfloat16 g_xinlo[NPAD * IND];
__device__ __align__(16) __nv_bfloat16 g_whi[WTOT];
__device__ __align__(16) __nv_bfloat16 g_wlo[WTOT];
__device__ float g_gate[Nn];
__device__ float g_pooled[Gg * Hh];
__device__ int   g_src[Mm];
__device__ int   g_dst[Mm];
__device__ int   g_deg[Nn];
__device__ int   g_incl[Nn];
__device__ int   g_bsum[NSCANB];
__device__ int   g_rowptr[Nn + 1];
__device__ int   g_cursor[Nn];
__device__ int   g_csrsrc[Mm];
__device__ int   g_bstart[Gg + 1];
__device__ int   g_idx64;

// ---------------- helpers ----------------
__device__ __forceinline__ uint32_t smem_to_u32(const void* smem_ptr) {
    uint32_t addr;
    asm("{ .reg .u64 tmp; cvta.to.shared.u64 tmp, %1; cvt.u32.u64 %0, tmp; }"
        : "=r"(addr) : "l"(smem_ptr));
    return addr;
}

__device__ __forceinline__ void cpa16(uint32_t dst, const void* src) {
    asm volatile("cp.async.cg.shared.global [%0], [%1], 16;" :: "r"(dst), "l"(src));
}

__device__ __forceinline__ void ldsm4(uint32_t* r, uint32_t addr) {
    asm volatile("ldmatrix.sync.aligned.m8n8.x4.shared.b16 {%0,%1,%2,%3}, [%4];"
        : "=r"(r[0]), "=r"(r[1]), "=r"(r[2]), "=r"(r[3]) : "r"(addr));
}

__device__ __forceinline__ void split2(float x, float y, uint32_t& hi, uint32_t& lo) {
    __nv_bfloat16 hx = __float2bfloat16_rn(x);
    __nv_bfloat16 hy = __float2bfloat16_rn(y);
    __nv_bfloat16 lx = __float2bfloat16_rn(x - __bfloat162float(hx));
    __nv_bfloat16 ly = __float2bfloat16_rn(y - __bfloat162float(hy));
    hi = ((uint32_t)__bfloat16_as_ushort(hy) << 16) | __bfloat16_as_ushort(hx);
    lo = ((uint32_t)__bfloat16_as_ushort(ly) << 16) | __bfloat16_as_ushort(lx);
}

__device__ __forceinline__ void mma16816(float* c, const uint32_t* a, uint32_t b0, uint32_t b1) {
    asm volatile(
        "mma.sync.aligned.m16n8k16.row.col.f32.bf16.bf16.f32 "
        "{%0,%1,%2,%3}, {%4,%5,%6,%7}, {%8,%9}, {%0,%1,%2,%3};"
        : "+f"(c[0]), "+f"(c[1]), "+f"(c[2]), "+f"(c[3])
        : "r"(a[0]), "r"(a[1]), "r"(a[2]), "r"(a[3]), "r"(b0), "r"(b1));
}

// ---------------- split kernels ----------------
__global__ void split_pairs_kernel(const float2* __restrict__ src,
                                   uint32_t* __restrict__ dhi, uint32_t* __restrict__ dlo, int n2) {
    int i = blockIdx.x * blockDim.x + threadIdx.x;
    if (i >= n2) return;
    float2 v = src[i];
    uint32_t h, l;
    split2(v.x, v.y, h, l);
    dhi[i] = h; dlo[i] = l;
}

__global__ void split_xin_kernel(const float2* __restrict__ src,
                                 uint32_t* __restrict__ dhi, uint32_t* __restrict__ dlo) {
    int i = blockIdx.x * blockDim.x + threadIdx.x;
    if (i >= NPAD * (IND / 2)) return;
    float2 v = (i < Nn * (IND / 2)) ? src[i] : make_float2(0.f, 0.f);
    uint32_t h, l;
    split2(v.x, v.y, h, l);
    dhi[i] = h; dlo[i] = l;
}

// ---------------- bf16 pipelined tensor GEMM (ldmatrix fragments) ----------------
// C[n,256] = A[n,K] @ W[256,K]^T + bias; A,W pre-split bf16 hi/lo.
// CTA 128x128, 8 warps (4x2), warp tile 32x64, K-chunk 32, 2-stage cp.async.
#define RS2 80
#define ST_AHI 0
#define ST_ALO 10240
#define ST_BHI 20480
#define ST_BLO 30720
#define ST_SZ  40960
#define GSM_TOT (2 * ST_SZ)

__global__ __launch_bounds__(256, 2)
void gemm_bf16_kernel(const __nv_bfloat16* __restrict__ Ahi, const __nv_bfloat16* __restrict__ Alo,
                      const __nv_bfloat16* __restrict__ Bhi, const __nv_bfloat16* __restrict__ Blo,
                      const float* __restrict__ bias, float* __restrict__ C,
                      uint32_t* __restrict__ Chi, uint32_t* __restrict__ Clo, int wsplit,
                      int n, int K, int relu) {
    extern __shared__ char smc[];
    uint32_t sb = smem_to_u32(smc);
    const int tid = threadIdx.x;
    const int wid = tid >> 5, lane = tid & 31;
    const int row0 = blockIdx.y * 128;
    const int col0 = blockIdx.x * 128;
    const int wr = (wid & 3) * 32;
    const int wc = (wid >> 2) * 64;
    const int lr = lane >> 2;
    const int lq = lane & 3;

    float acc[16][4];
#pragma unroll
    for (int t = 0; t < 16; t++)
#pragma unroll
        for (int q = 0; q < 4; q++) acc[t][q] = 0.f;

    const int nc = K >> 5;

    auto issue = [&](int kc, int stage) {
        const int kOff = kc * 32;
        const uint32_t s0 = sb + stage * ST_SZ;
#pragma unroll
        for (int it = 0; it < 2; it++) {
            int i = tid + it * 256;      // 0..511
            int r = i >> 2, pc = i & 3;
            uint32_t d = (uint32_t)(r * RS2 + pc * 16);
            size_t aoff = (size_t)(row0 + r) * K + kOff + pc * 8;
            cpa16(s0 + ST_AHI + d, Ahi + aoff);
            cpa16(s0 + ST_ALO + d, Alo + aoff);
            size_t boff = (size_t)(col0 + r) * K + kOff + pc * 8;
            cpa16(s0 + ST_BHI + d, Bhi + boff);
            cpa16(s0 + ST_BLO + d, Blo + boff);
        }
    };

    issue(0, 0);
    asm volatile("cp.async.commit_group;" ::: "memory");

    // precomputed ldmatrix lane addressing offsets (within a stage)
    const uint32_t a_lane = (uint32_t)((lane & 15) * RS2 + ((lane >> 4) & 1) * 16);
    const uint32_t b_lane = (uint32_t)((((lane >> 4) & 1) * 8 + (lane & 7)) * RS2 + ((lane >> 3) & 1) * 16);

    for (int kc = 0; kc < nc; kc++) {
        if (kc + 1 < nc) issue(kc + 1, (kc + 1) & 1);
        asm volatile("cp.async.commit_group;" ::: "memory");
        asm volatile("cp.async.wait_group 1;" ::: "memory");
        __syncthreads();
        const uint32_t st = sb + (kc & 1) * ST_SZ;
#pragma unroll
        for (int ks = 0; ks < 2; ks++) {
            const uint32_t kso = (uint32_t)(ks * 32);
            uint32_t ah[2][4], al[2][4];
#pragma unroll
            for (int mt = 0; mt < 2; mt++) {
                uint32_t ra = st + ST_AHI + (uint32_t)((wr + mt * 16) * RS2) + a_lane + kso;
                ldsm4(ah[mt], ra);
                ldsm4(al[mt], ra + (ST_ALO - ST_AHI));
            }
#pragma unroll
            for (int ntp = 0; ntp < 4; ntp++) {
                uint32_t rb = st + ST_BHI + (uint32_t)((wc + ntp * 16) * RS2) + b_lane + kso;
                uint32_t bh[4], bl[4];
                ldsm4(bh, rb);
                ldsm4(bl, rb + (ST_BLO - ST_BHI));
#pragma unroll
                for (int mt = 0; mt < 2; mt++) {
                    float* ce = acc[mt * 8 + ntp * 2];
                    mma16816(ce, ah[mt], bh[0], bh[1]);
                    mma16816(ce, ah[mt], bl[0], bl[1]);
                    mma16816(ce, al[mt], bh[0], bh[1]);
                    float* co = acc[mt * 8 + ntp * 2 + 1];
                    mma16816(co, ah[mt], bh[2], bh[3]);
                    mma16816(co, ah[mt], bl[2], bl[3]);
                    mma16816(co, al[mt], bh[2], bh[3]);
                }
            }
        }
        __syncthreads();
    }

    // ---- epilogue ----
#pragma unroll
    for (int mt = 0; mt < 2; mt++) {
#pragma unroll
        for (int nt = 0; nt < 8; nt++) {
            const float* c = acc[mt * 8 + nt];
            int col = col0 + wc + nt * 8 + lq * 2;
            float b0 = bias[col], b1 = bias[col + 1];
            int r0 = row0 + wr + mt * 16 + lr;
            int r1 = r0 + 8;
            float2 o;
            uint32_t h, l;
            if (r0 < n) {
                o.x = c[0] + b0; o.y = c[1] + b1;
                if (relu) { o.x = fmaxf(o.x, 0.f); o.y = fmaxf(o.y, 0.f); }
                *(float2*)&C[(size_t)r0 * Hh + col] = o;
                if (wsplit) {
                    split2(o.x, o.y, h, l);
                    Chi[(size_t)r0 * 128 + (col >> 1)] = h;
                    Clo[(size_t)r0 * 128 + (col >> 1)] = l;
                }
            }
            if (r1 < n) {
                o.x = c[2] + b0; o.y = c[3] + b1;
                if (relu) { o.x = fmaxf(o.x, 0.f); o.y = fmaxf(o.y, 0.f); }
                *(float2*)&C[(size_t)r1 * Hh + col] = o;
                if (wsplit) {
                    split2(o.x, o.y, h, l);
                    Chi[(size_t)r1 * 128 + (col >> 1)] = h;
                    Clo[(size_t)r1 * 128 + (col >> 1)] = l;
                }
            }
        }
    }
}

// ---------------- index width detection ----------------
__global__ void detect_kernel(const void* ei) {
    const long long* p = (const long long*)ei;
    int ok = 1;
    for (int i = 0; i < 64; i++) {
        long long v = p[i];
        if (v < 0 || v >= Nn) { ok = 0; break; }
    }
    g_idx64 = ok;
}

__global__ void zero_deg_kernel() {
    int i = blockIdx.x * blockDim.x + threadIdx.x;
    if (i < Nn) g_deg[i] = 0;
}

__global__ void convert_count_kernel(const void* ei) {
    int m = blockIdx.x * blockDim.x + threadIdx.x;
    if (m >= Mm) return;
    int is64 = g_idx64;
    int s, d;
    if (m < Ee) {
        if (is64) { s = (int)((const long long*)ei)[m]; d = (int)((const long long*)ei)[(long long)Ee + m]; }
        else      { s = ((const int*)ei)[m];            d = ((const int*)ei)[Ee + m]; }
    } else { s = d = m - Ee; }
    g_src[m] = s;
    g_dst[m] = d;
    atomicAdd(&g_deg[d], 1);
}

__global__ void scan1_kernel() {
    __shared__ int smi[SCANB];
    int i = blockIdx.x * SCANB + threadIdx.x;
    int v = (i < Nn) ? g_deg[i] : 0;
    smi[threadIdx.x] = v;
    __syncthreads();
    for (int o = 1; o < SCANB; o <<= 1) {
        int t = (threadIdx.x >= o) ? smi[threadIdx.x - o] : 0;
        __syncthreads();
        smi[threadIdx.x] += t;
        __syncthreads();
    }
    if (i < Nn) g_incl[i] = smi[threadIdx.x];
    if (threadIdx.x == SCANB - 1) g_bsum[blockIdx.x] = smi[SCANB - 1];
}

__global__ void scan2_kernel() {
    __shared__ int smi[64];
    int t = threadIdx.x;
    int v = (t < NSCANB) ? g_bsum[t] : 0;
    smi[t] = v;
    __syncthreads();
    for (int o = 1; o < 64; o <<= 1) {
        int u = (t >= o) ? smi[t - o] : 0;
        __syncthreads();
        smi[t] += u;
        __syncthreads();
    }
    if (t < NSCANB) g_bsum[t] = smi[t];
}

__global__ void scan3_kernel() {
    int i = blockIdx.x * blockDim.x + threadIdx.x;
    if (i >= Nn) return;
    int b = i >> 10;
    int excl = g_incl[i] - g_deg[i] + (b ? g_bsum[b - 1] : 0);
    g_rowptr[i] = excl;
    g_cursor[i] = excl;
    if (i == 0) g_rowptr[Nn] = Mm;
}

__global__ void csr_fill_kernel() {
    int m = blockIdx.x * blockDim.x + threadIdx.x;
    if (m >= Mm) return;
    int d = g_dst[m];
    int pos = atomicAdd(&g_cursor[d], 1);
    g_csrsrc[pos] = g_src[m];
}

// ---------------- fused edge phase (warp/dst): unroll-2 online softmax + LN + residual + split
__global__ __launch_bounds__(256)
void edge_fused_kernel(const int* __restrict__ rowptr, const int* __restrict__ csrsrc,
                       const float4* __restrict__ xl, const float4* __restrict__ xr,
                       const float4* __restrict__ att4,
                       const float4* __restrict__ bias_c4,
                       const float4* __restrict__ lg4, const float4* __restrict__ lb4,
                       float4* __restrict__ x,
                       uint32_t* __restrict__ xhi32, uint32_t* __restrict__ xlo32) {
    int d = (blockIdx.x * blockDim.x + threadIdx.x) >> 5;
    int lane = threadIdx.x & 31;
    if (d >= Nn) return;

    float4 r0 = xr[(size_t)d * 64 + lane];
    float4 r1 = xr[(size_t)d * 64 + 32 + lane];
    float4 t0 = att4[lane];
    float4 t1 = att4[32 + lane];

    float m = -INFINITY, s = 0.f;
    float4 acc0 = make_float4(0,0,0,0), acc1 = make_float4(0,0,0,0);

    int p0 = rowptr[d], p1 = rowptr[d + 1];
    int p = p0;
    // pairwise: both gathers in flight before the reduce chains; one rescale per pair
    for (; p + 1 < p1; p += 2) {
        int sa = csrsrc[p], sb2 = csrsrc[p + 1];
        float4 c0 = xl[(size_t)sa * 64 + lane];
        float4 c1 = xl[(size_t)sa * 64 + 32 + lane];
        float4 d0 = xl[(size_t)sb2 * 64 + lane];
        float4 d1 = xl[(size_t)sb2 * 64 + 32 + lane];
        float e1 = 0.f, e2 = 0.f, v;
        v = c0.x + r0.x; v = (v > 0.f) ? v : 0.2f * v; e1 = fmaf(v, t0.x, e1);
        v = d0.x + r0.x; v = (v > 0.f) ? v : 0.2f * v; e2 = fmaf(v, t0.x, e2);
        v = c0.y + r0.y; v = (v > 0.f) ? v : 0.2f * v; e1 = fmaf(v, t0.y, e1);
        v = d0.y + r0.y; v = (v > 0.f) ? v : 0.2f * v; e2 = fmaf(v, t0.y, e2);
        v = c0.z + r0.z; v = (v > 0.f) ? v : 0.2f * v; e1 = fmaf(v, t0.z, e1);
        v = d0.z + r0.z; v = (v > 0.f) ? v : 0.2f * v; e2 = fmaf(v, t0.z, e2);
        v = c0.w + r0.w; v = (v > 0.f) ? v : 0.2f * v; e1 = fmaf(v, t0.w, e1);
        v = d0.w + r0.w; v = (v > 0.f) ? v : 0.2f * v; e2 = fmaf(v, t0.w, e2);
        v = c1.x + r1.x; v = (v > 0.f) ? v : 0.2f * v; e1 = fmaf(v, t1.x, e1);
        v = d1.x + r1.x; v = (v > 0.f) ? v : 0.2f * v; e2 = fmaf(v, t1.x, e2);
        v = c1.y + r1.y; v = (v > 0.f) ? v : 0.2f * v; e1 = fmaf(v, t1.y, e1);
        v = d1.y + r1.y; v = (v > 0.f) ? v : 0.2f * v; e2 = fmaf(v, t1.y, e2);
        v = c1.z + r1.z; v = (v > 0.f) ? v : 0.2f * v; e1 = fmaf(v, t1.z, e1);
        v = d1.z + r1.z; v = (v > 0.f) ? v : 0.2f * v; e2 = fmaf(v, t1.z, e2);
        v = c1.w + r1.w; v = (v > 0.f) ? v : 0.2f * v; e1 = fmaf(v, t1.w, e1);
        v = d1.w + r1.w; v = (v > 0.f) ? v : 0.2f * v; e2 = fmaf(v, t1.w, e2);
#pragma unroll
        for (int o = 16; o; o >>= 1) {
            e1 += __shfl_xor_sync(0xffffffffu, e1, o);
            e2 += __shfl_xor_sync(0xffffffffu, e2, o);
        }
        float mn = fmaxf(m, fmaxf(e1, e2));
        float cc = __expf(m - mn);                 // first pair: exp(-inf)=0
        float w1 = __expf(e1 - mn);
        float w2 = __expf(e2 - mn);
        s = s * cc + w1 + w2;
        acc0.x = acc0.x * cc + w1 * c0.x + w2 * d0.x;
        acc0.y = acc0.y * cc + w1 * c0.y + w2 * d0.y;
        acc0.z = acc0.z * cc + w1 * c0.z + w2 * d0.z;
        acc0.w = acc0.w * cc + w1 * c0.w + w2 * d0.w;
        acc1.x = acc1.x * cc + w1 * c1.x + w2 * d1.x;
        acc1.y = acc1.y * cc + w1 * c1.y + w2 * d1.y;
        acc1.z = acc1.z * cc + w1 * c1.z + w2 * d1.z;
        acc1.w = acc1.w * cc + w1 * c1.w + w2 * d1.w;
        m = mn;
    }
    if (p < p1) {   // tail edge
        int sa = csrsrc[p];
        float4 c0 = xl[(size_t)sa * 64 + lane];
        float4 c1 = xl[(size_t)sa * 64 + 32 + lane];
        float e = 0.f, v;
        v = c0.x + r0.x; v = (v > 0.f) ? v : 0.2f * v; e = fmaf(v, t0.x, e);
        v = c0.y + r0.y; v = (v > 0.f) ? v : 0.2f * v; e = fmaf(v, t0.y, e);
        v = c0.z + r0.z; v = (v > 0.f) ? v : 0.2f * v; e = fmaf(v, t0.z, e);
        v = c0.w + r0.w; v = (v > 0.f) ? v : 0.2f * v; e = fmaf(v, t0.w, e);
        v = c1.x + r1.x; v = (v > 0.f) ? v : 0.2f * v; e = fmaf(v, t1.x, e);
        v = c1.y + r1.y; v = (v > 0.f) ? v : 0.2f * v; e = fmaf(v, t1.y, e);
        v = c1.z + r1.z; v = (v > 0.f) ? v : 0.2f * v; e = fmaf(v, t1.z, e);
        v = c1.w + r1.w; v = (v > 0.f) ? v : 0.2f * v; e = fmaf(v, t1.w, e);
#pragma unroll
        for (int o = 16; o; o >>= 1) e += __shfl_xor_sync(0xffffffffu, e, o);
        float mn = fmaxf(m, e);
        float cc = __expf(m - mn);
        float w = __expf(e - mn);
        s = s * cc + w;
        acc0.x = acc0.x * cc + w * c0.x; acc0.y = acc0.y * cc + w * c0.y;
        acc0.z = acc0.z * cc + w * c0.z; acc0.w = acc0.w * cc + w * c0.w;
        acc1.x = acc1.x * cc + w * c1.x; acc1.y = acc1.y * cc + w * c1.y;
        acc1.z = acc1.z * cc + w * c1.z; acc1.w = acc1.w * cc + w * c1.w;
        m = mn;
    }

    float inv = 1.f / s;
    float4 bc0 = bias_c4[lane], bc1 = bias_c4[32 + lane];
    float v0x = acc0.x * inv + bc0.x, v0y = acc0.y * inv + bc0.y;
    float v0z = acc0.z * inv + bc0.z, v0w = acc0.w * inv + bc0.w;
    float v1x = acc1.x * inv + bc1.x, v1y = acc1.y * inv + bc1.y;
    float v1z = acc1.z * inv + bc1.z, v1w = acc1.w * inv + bc1.w;

    float sum = v0x + v0y + v0z + v0w + v1x + v1y + v1z + v1w;
#pragma unroll
    for (int o = 16; o; o >>= 1) sum += __shfl_xor_sync(0xffffffffu, sum, o);
    float mu = sum * (1.f / Hh);
    float d0x = v0x - mu, d0y = v0y - mu, d0z = v0z - mu, d0w = v0w - mu;
    float d1x = v1x - mu, d1y = v1y - mu, d1z = v1z - mu, d1w = v1w - mu;
    float vsum = d0x*d0x + d0y*d0y + d0z*d0z + d0w*d0w + d1x*d1x + d1y*d1y + d1z*d1z + d1w*d1w;
#pragma unroll
    for (int o = 16; o; o >>= 1) vsum += __shfl_xor_sync(0xffffffffu, vsum, o);
    float rs = rsqrtf(vsum * (1.f / Hh) + 1e-5f);

    float4 lg0 = lg4[lane], lg1 = lg4[32 + lane];
    float4 lb0 = lb4[lane], lb1 = lb4[32 + lane];
    float4 xr0 = x[(size_t)d * 64 + lane];
    float4 xr1 = x[(size_t)d * 64 + 32 + lane];
    float4 o0, o1;
    o0.x = fmaxf(d0x * rs * lg0.x + lb0.x, 0.f) + xr0.x;
    o0.y = fmaxf(d0y * rs * lg0.y + lb0.y, 0.f) + xr0.y;
    o0.z = fmaxf(d0z * rs * lg0.z + lb0.z, 0.f) + xr0.z;
    o0.w = fmaxf(d0w * rs * lg0.w + lb0.w, 0.f) + xr0.w;
    o1.x = fmaxf(d1x * rs * lg1.x + lb1.x, 0.f) + xr1.x;
    o1.y = fmaxf(d1y * rs * lg1.y + lb1.y, 0.f) + xr1.y;
    o1.z = fmaxf(d1z * rs * lg1.z + lb1.z, 0.f) + xr1.z;
    o1.w = fmaxf(d1w * rs * lg1.w + lb1.w, 0.f) + xr1.w;
    x[(size_t)d * 64 + lane] = o0;
    x[(size_t)d * 64 + 32 + lane] = o1;

    // bf16 hi/lo split for next layer's GEMM A operand
    size_t b32 = (size_t)d * 128 + 2 * lane;
    uint32_t h, l;
    split2(o0.x, o0.y, h, l); xhi32[b32]      = h; xlo32[b32]      = l;
    split2(o0.z, o0.w, h, l); xhi32[b32 + 1]  = h; xlo32[b32 + 1]  = l;
    split2(o1.x, o1.y, h, l); xhi32[b32 + 64] = h; xlo32[b32 + 64] = l;
    split2(o1.z, o1.w, h, l); xhi32[b32 + 65] = h; xlo32[b32 + 65] = l;
}

// ---------------- gate dot ----------------
__global__ void gate_dot_kernel(const float4* __restrict__ hid, const float4* __restrict__ Wg2,
                                const float* __restrict__ bg2, float* __restrict__ gate) {
    int w = (blockIdx.x * blockDim.x + threadIdx.x) >> 5;
    int lane = threadIdx.x & 31;
    if (w >= Nn) return;
    const float4* p = hid + (size_t)w * 64;
    float sum = 0.f;
#pragma unroll
    for (int j = lane; j < 64; j += 32) {
        float4 a = p[j], t = Wg2[j];
        sum = fmaf(a.x, t.x, fmaf(a.y, t.y, fmaf(a.z, t.z, fmaf(a.w, t.w, sum))));
    }
#pragma unroll
    for (int o = 16; o; o >>= 1) sum += __shfl_xor_sync(0xffffffffu, sum, o);
    if (lane == 0) gate[w] = sum + bg2[0];
}

// ---------------- batch segment boundaries ----------------
__global__ void bstart_kernel(const void* __restrict__ batch) {
    int g = threadIdx.x;
    if (g > Gg) return;
    if (g == Gg) { g_bstart[Gg] = Nn; return; }
    int is64 = g_idx64;
    int lo = 0, hi = Nn;
    while (lo < hi) {
        int mid = (lo + hi) >> 1;
        long long v = is64 ? ((const long long*)batch)[mid] : (long long)((const int*)batch)[mid];
        if (v < g) lo = mid + 1; else hi = mid;
    }
    g_bstart[g] = lo;
}

// ---------------- segmented softmax pooling ----------------
__global__ __launch_bounds__(256)
void segpool_kernel(const float* __restrict__ gate, const float* __restrict__ x,
                    float* __restrict__ pooled) {
    int g = blockIdx.x, tid = threadIdx.x;
    int s = g_bstart[g], e = g_bstart[g + 1];
    __shared__ float red[8];
    __shared__ float ws[256];
    if (s >= e) { pooled[(size_t)g * Hh + tid] = 0.f; return; }

    float m = -INFINITY;
    for (int i = s + tid; i < e; i += 256) m = fmaxf(m, gate[i]);
#pragma unroll
    for (int o = 16; o; o >>= 1) m = fmaxf(m, __shfl_xor_sync(0xffffffffu, m, o));
    if ((tid & 31) == 0) red[tid >> 5] = m;
    __syncthreads();
    m = fmaxf(fmaxf(fmaxf(red[0], red[1]), fmaxf(red[2], red[3])),
              fmaxf(fmaxf(red[4], red[5]), fmaxf(red[6], red[7])));
    __syncthreads();

    float sum = 0.f;
    for (int i = s + tid; i < e; i += 256) sum += __expf(gate[i] - m);
#pragma unroll
    for (int o = 16; o; o >>= 1) sum += __shfl_xor_sync(0xffffffffu, sum, o);
    if ((tid & 31) == 0) red[tid >> 5] = sum;
    __syncthreads();
    sum = red[0] + red[1] + red[2] + red[3] + red[4] + red[5] + red[6] + red[7];
    __syncthreads();

    float acc = 0.f;
    for (int i0 = s; i0 < e; i0 += 256) {
        int n = min(256, e - i0);
        if (tid < n) ws[tid] = __expf(gate[i0 + tid] - m);
        __syncthreads();
        for (int j = 0; j < n; j++) acc = fmaf(ws[j], x[(size_t)(i0 + j) * Hh + tid], acc);
        __syncthreads();
    }
    pooled[(size_t)g * Hh + tid] = acc / sum;
}

// ---------------- head ----------------
__global__ void head_kernel(const float* __restrict__ pooled,
                            const float* __restrict__ Ws, const float* __restrict__ bs,
                            const float* __restrict__ Wc, const float* __restrict__ bc,
                            const float* __restrict__ Wr1, const float* __restrict__ br1,
                            const float* __restrict__ Wr2, const float* __restrict__ br2,
                            float* __restrict__ out) {
    int g = blockIdx.x, t = threadIdx.x;
    __shared__ float sp[Hh];
    __shared__ float sz[Hh];
    __shared__ float sr[128];
    sp[t] = pooled[(size_t)g * Hh + t];
    __syncthreads();
    float acc = bs[t];
#pragma unroll 8
    for (int k = 0; k < Hh; k++) acc = fmaf(sp[k], Ws[(size_t)t * Hh + k], acc);
    sz[t] = fmaxf(acc, 0.f);
    __syncthreads();
    if (t < NBc) {
        float a2 = bc[t];
#pragma unroll 8
        for (int k = 0; k < Hh; k++) a2 = fmaf(sz[k], Wc[(size_t)t * Hh + k], a2);
        out[(size_t)g * NBc + t] = a2;
    }
    if (t < 128) {
        float a3 = br1[t];
#pragma unroll 8
        for (int k = 0; k < Hh; k++) a3 = fmaf(sz[k], Wr1[(size_t)t * Hh + k], a3);
        sr[t] = fmaxf(a3, 0.f);
    }
    __syncthreads();
    if (t < 128) {
        float v = sr[t] * Wr2[t];
#pragma unroll
        for (int o = 16; o; o >>= 1) v += __shfl_xor_sync(0xffffffffu, v, o);
        if ((t & 31) == 0) sp[t >> 5] = v;
    }
    __syncthreads();
    if (t == 0) {
        float tot = sp[0] + sp[1] + sp[2] + sp[3] + br2[0];
        out[(size_t)Gg * NBc + g] = tanhf(tot);
    }
}

// ---------------- launch ----------------
extern "C" void kernel_launch(void* const* d_in, const int* in_sizes, int n_in,
                              void* d_out, int out_size) {
    const float* x_in   = (const float*)d_in[0];
    const void*  ei     = d_in[1];
    const void*  batch  = d_in[2];
    const float* W_in   = (const float*)d_in[3];
    const float* b_in   = (const float*)d_in[4];
    const float* Wl     = (const float*)d_in[5];
    const float* bl     = (const float*)d_in[6];
    const float* Wr     = (const float*)d_in[7];
    const float* br     = (const float*)d_in[8];
    const float* att    = (const float*)d_in[9];
    const float* bias_c = (const float*)d_in[10];
    const float* ln_g   = (const float*)d_in[11];
    const float* ln_b   = (const float*)d_in[12];
    const float* Wg1    = (const float*)d_in[13];
    const float* bg1    = (const float*)d_in[14];
    const float* Wg2    = (const float*)d_in[15];
    const float* bg2    = (const float*)d_in[16];
    const float* Ws     = (const float*)d_in[17];
    const float* bs     = (const float*)d_in[18];
    const float* Wc     = (const float*)d_in[19];
    const float* bc     = (const float*)d_in[20];
    const float* Wr1    = (const float*)d_in[21];
    const float* br1    = (const float*)d_in[22];
    const float* Wr2    = (const float*)d_in[23];
    const float* br2    = (const float*)d_in[24];
    float* out = (float*)d_out;

    float *px, *pxl, *pxr, *pgate, *ppooled;
    __nv_bfloat16 *pxhi, *pxlo, *pxinhi, *pxinlo, *pwhi, *pwlo;
    int *prowptr, *pcsrsrc;
    cudaGetSymbolAddress((void**)&px,      g_x);
    cudaGetSymbolAddress((void**)&pxl,     g_xl);
    cudaGetSymbolAddress((void**)&pxr,     g_xr);
    cudaGetSymbolAddress((void**)&pxhi,    g_xhi);
    cudaGetSymbolAddress((void**)&pxlo,    g_xlo);
    cudaGetSymbolAddress((void**)&pxinhi,  g_xinhi);
    cudaGetSymbolAddress((void**)&pxinlo,  g_xinlo);
    cudaGetSymbolAddress((void**)&pwhi,    g_whi);
    cudaGetSymbolAddress((void**)&pwlo,    g_wlo);
    cudaGetSymbolAddress((void**)&pgate,   g_gate);
    cudaGetSymbolAddress((void**)&ppooled, g_pooled);
    cudaGetSymbolAddress((void**)&prowptr, g_rowptr);
    cudaGetSymbolAddress((void**)&pcsrsrc, g_csrsrc);

    cudaFuncSetAttribute(gemm_bf16_kernel, cudaFuncAttributeMaxDynamicSharedMemorySize, GSM_TOT);

    const dim3 gemm_grid(2, (Nn + 127) / 128);
    const int NODE_W_BLOCKS = (Nn * 32 + 255) / 256;

    // ---- weight + input splits ----
    split_pairs_kernel<<<(16384/2 + 255)/256, 256>>>((const float2*)W_in,
        (uint32_t*)(pwhi + WOFF_IN), (uint32_t*)(pwlo + WOFF_IN), 16384/2);
    split_pairs_kernel<<<(262144/2 + 255)/256, 256>>>((const float2*)Wl,
        (uint32_t*)(pwhi + WOFF_L), (uint32_t*)(pwlo + WOFF_L), 262144/2);
    split_pairs_kernel<<<(262144/2 + 255)/256, 256>>>((const float2*)Wr,
        (uint32_t*)(pwhi + WOFF_R), (uint32_t*)(pwlo + WOFF_R), 262144/2);
    split_pairs_kernel<<<(65536/2 + 255)/256, 256>>>((const float2*)Wg1,
        (uint32_t*)(pwhi + WOFF_G1), (uint32_t*)(pwlo + WOFF_G1), 65536/2);
    split_xin_kernel<<<(NPAD*(IND/2) + 255)/256, 256>>>((const float2*)x_in,
        (uint32_t*)pxinhi, (uint32_t*)pxinlo);

    // ---- CSR build ----
    detect_kernel<<<1, 1>>>(ei);
    zero_deg_kernel<<<(Nn + 255) / 256, 256>>>();
    convert_count_kernel<<<(Mm + 255) / 256, 256>>>(ei);
    scan1_kernel<<<NSCANB, SCANB>>>();
    scan2_kernel<<<1, 64>>>();
    scan3_kernel<<<(Nn + 255) / 256, 256>>>();
    csr_fill_kernel<<<(Mm + 255) / 256, 256>>>();
    bstart_kernel<<<1, Gg + 1>>>(batch);

    // ---- input projection (K=64): writes px fp32 AND split for layer-0 GEMMs ----
    gemm_bf16_kernel<<<gemm_grid, 256, GSM_TOT>>>(pxinhi, pxinlo,
        pwhi + WOFF_IN, pwlo + WOFF_IN, b_in, px,
        (uint32_t*)pxhi, (uint32_t*)pxlo, 1, Nn, IND, 0);

    // ---- GAT layers ----
    for (int l = 0; l < Ll; l++) {
        gemm_bf16_kernel<<<gemm_grid, 256, GSM_TOT>>>(pxhi, pxlo,
            pwhi + WOFF_L + (size_t)l * Hh * Hh, pwlo + WOFF_L + (size_t)l * Hh * Hh,
            bl + l * Hh, pxl, nullptr, nullptr, 0, Nn, Hh, 0);
        gemm_bf16_kernel<<<gemm_grid, 256, GSM_TOT>>>(pxhi, pxlo,
            pwhi + WOFF_R + (size_t)l * Hh * Hh, pwlo + WOFF_R + (size_t)l * Hh * Hh,
            br + l * Hh, pxr, nullptr, nullptr, 0, Nn, Hh, 0);
        edge_fused_kernel<<<NODE_W_BLOCKS, 256>>>(prowptr, pcsrsrc,
            (const float4*)pxl, (const float4*)pxr,
            (const float4*)(att + l * Hh),
            (const float4*)(bias_c + l * Hh),
            (const float4*)(ln_g + l * Hh), (const float4*)(ln_b + l * Hh),
            (float4*)px, (uint32_t*)pxhi, (uint32_t*)pxlo);
    }

    // ---- readout ----
    gemm_bf16_kernel<<<gemm_grid, 256, GSM_TOT>>>(pxhi, pxlo,
        pwhi + WOFF_G1, pwlo + WOFF_G1, bg1, pxl, nullptr, nullptr, 0, Nn, Hh, 1);
    gate_dot_kernel<<<NODE_W_BLOCKS, 256>>>((const float4*)pxl, (const float4*)Wg2, bg2, pgate);
    segpool_kernel<<<Gg, 256>>>(pgate, px, ppooled);
    head_kernel<<<Gg, Hh>>>(ppooled, Ws, bs, Wc, bc, Wr1, br1, Wr2, br2, out);
}

// round 15
// speedup vs baseline: 1.0973x; 1.0350x over previous
#include <cuda_runtime.h>
#include <cuda_bf16.h>
#include <math.h>
#include <stdint.h>

#define Nn 50000
#define Ee 300000
#define Mm (Ee + Nn)
#define NPAD 50048          // Nn rounded up to 128
#define IND 64
#define Hh 256
#define Ll 4
#define NBc 181
#define Gg 64
#define SCANB 1024
#define NSCANB ((Nn + SCANB - 1) / SCANB)

// weight split offsets (elements)
#define WOFF_IN  0
#define WOFF_LR  16384
#define WOFF_G1  (16384 + 4 * 512 * 256)
#define WTOT     (16384 + 4 * 512 * 256 + 65536)

// ---------------- scratch (device globals; no allocation allowed) ----------------
__device__ float g_x[Nn * Hh];
__device__ float g_xlr[Nn * 512];       // fused xl|xr per node
__device__ float g_xl[Nn * Hh];         // gate hidden
__device__ __align__(16) __nv_bfloat16 g_xhi[NPAD * Hh];
__device__ __align__(16) __nv_bfloat16 g_xlo[NPAD * Hh];
__device__ __align__(16) __nv_bfloat16 g_xinhi[NPAD * IND];
__device__ __align__(16) __nv_bfloat16 g_xinlo[NPAD * IND];
__device__ __align__(16) __nv_bfloat16 g_whi[WTOT];
__device__ __align__(16) __nv_bfloat16 g_wlo[WTOT];
__device__ float g_biascat[Ll * 512];
__device__ float g_gate[Nn];
__device__ float g_pooled[Gg * Hh];
__device__ int   g_src[Mm];
__device__ int   g_dst[Mm];
__device__ int   g_deg[Nn];
__device__ int   g_incl[Nn];
__device__ int   g_bsum[NSCANB];
__device__ int   g_rowptr[Nn + 1];
__device__ int   g_cursor[Nn];
__device__ int   g_csrsrc[Mm];
__device__ int   g_bstart[Gg + 1];
__device__ int   g_idx64;

// ---------------- helpers ----------------
__device__ __forceinline__ uint32_t smem_to_u32(const void* smem_ptr) {
    uint32_t addr;
    asm("{ .reg .u64 tmp; cvta.to.shared.u64 tmp, %1; cvt.u32.u64 %0, tmp; }"
        : "=r"(addr) : "l"(smem_ptr));
    return addr;
}

__device__ __forceinline__ void cpa16(uint32_t dst, const void* src) {
    asm volatile("cp.async.cg.shared.global [%0], [%1], 16;" :: "r"(dst), "l"(src));
}

__device__ __forceinline__ void ldsm4(uint32_t* r, uint32_t addr) {
    asm volatile("ldmatrix.sync.aligned.m8n8.x4.shared.b16 {%0,%1,%2,%3}, [%4];"
        : "=r"(r[0]), "=r"(r[1]), "=r"(r[2]), "=r"(r[3]) : "r"(addr));
}

__device__ __forceinline__ void split2(float x, float y, uint32_t& hi, uint32_t& lo) {
    __nv_bfloat16 hx = __float2bfloat16_rn(x);
    __nv_bfloat16 hy = __float2bfloat16_rn(y);
    __nv_bfloat16 lx = __float2bfloat16_rn(x - __bfloat162float(hx));
    __nv_bfloat16 ly = __float2bfloat16_rn(y - __bfloat162float(hy));
    hi = ((uint32_t)__bfloat16_as_ushort(hy) << 16) | __bfloat16_as_ushort(hx);
    lo = ((uint32_t)__bfloat16_as_ushort(ly) << 16) | __bfloat16_as_ushort(lx);
}

__device__ __forceinline__ void mma16816(float* c, const uint32_t* a, uint32_t b0, uint32_t b1) {
    asm volatile(
        "mma.sync.aligned.m16n8k16.row.col.f32.bf16.bf16.f32 "
        "{%0,%1,%2,%3}, {%4,%5,%6,%7}, {%8,%9}, {%0,%1,%2,%3};"
        : "+f"(c[0]), "+f"(c[1]), "+f"(c[2]), "+f"(c[3])
        : "r"(a[0]), "r"(a[1]), "r"(a[2]), "r"(a[3]), "r"(b0), "r"(b1));
}

// ---------------- split kernels ----------------
__global__ void split_pairs_kernel(const float2* __restrict__ src,
                                   uint32_t* __restrict__ dhi, uint32_t* __restrict__ dlo, int n2) {
    int i = blockIdx.x * blockDim.x + threadIdx.x;
    if (i >= n2) return;
    float2 v = src[i];
    uint32_t h, l;
    split2(v.x, v.y, h, l);
    dhi[i] = h; dlo[i] = l;
}

// concatenated [L][512][256] from Wl [L][256][256] + Wr [L][256][256]
__global__ void split_wcat_kernel(const float2* __restrict__ Wl, const float2* __restrict__ Wr,
                                  uint32_t* __restrict__ dhi, uint32_t* __restrict__ dlo) {
    int i = blockIdx.x * blockDim.x + threadIdx.x;       // pair index over L*512*128
    if (i >= Ll * 512 * 128) return;
    int l = i / (512 * 128);
    int rem = i - l * 512 * 128;
    int r = rem >> 7, c2 = rem & 127;
    float2 v = (r < 256) ? Wl[((size_t)l * 256 + r) * 128 + c2]
                         : Wr[((size_t)l * 256 + (r - 256)) * 128 + c2];
    uint32_t h, lo;
    split2(v.x, v.y, h, lo);
    dhi[i] = h; dlo[i] = lo;
}

__global__ void biascat_kernel(const float* __restrict__ bl, const float* __restrict__ br) {
    int i = blockIdx.x * blockDim.x + threadIdx.x;
    if (i >= Ll * 512) return;
    int l = i >> 9, c = i & 511;
    g_biascat[i] = (c < 256) ? bl[l * 256 + c] : br[l * 256 + c - 256];
}

__global__ void split_xin_kernel(const float2* __restrict__ src,
                                 uint32_t* __restrict__ dhi, uint32_t* __restrict__ dlo) {
    int i = blockIdx.x * blockDim.x + threadIdx.x;
    if (i >= NPAD * (IND / 2)) return;
    float2 v = (i < Nn * (IND / 2)) ? src[i] : make_float2(0.f, 0.f);
    uint32_t h, l;
    split2(v.x, v.y, h, l);
    dhi[i] = h; dlo[i] = l;
}

// ---------------- bf16 pipelined tensor GEMM (ldmatrix fragments) ----------------
#define RS2 80
#define ST_AHI 0
#define ST_ALO 10240
#define ST_BHI 20480
#define ST_BLO 30720
#define ST_SZ  40960
#define GSM_TOT (2 * ST_SZ)

__global__ __launch_bounds__(256, 2)
void gemm_bf16_kernel(const __nv_bfloat16* __restrict__ Ahi, const __nv_bfloat16* __restrict__ Alo,
                      const __nv_bfloat16* __restrict__ Bhi, const __nv_bfloat16* __restrict__ Blo,
                      const float* __restrict__ bias, float* __restrict__ C, int ldc,
                      uint32_t* __restrict__ Chi, uint32_t* __restrict__ Clo, int wsplit,
                      int n, int K, int relu) {
    extern __shared__ char smc[];
    uint32_t sb = smem_to_u32(smc);
    const int tid = threadIdx.x;
    const int wid = tid >> 5, lane = tid & 31;
    const int row0 = blockIdx.y * 128;
    const int col0 = blockIdx.x * 128;
    const int wr = (wid & 3) * 32;
    const int wc = (wid >> 2) * 64;
    const int lr = lane >> 2;
    const int lq = lane & 3;

    float acc[16][4];
#pragma unroll
    for (int t = 0; t < 16; t++)
#pragma unroll
        for (int q = 0; q < 4; q++) acc[t][q] = 0.f;

    const int nc = K >> 5;

    auto issue = [&](int kc, int stage) {
        const int kOff = kc * 32;
        const uint32_t s0 = sb + stage * ST_SZ;
#pragma unroll
        for (int it = 0; it < 2; it++) {
            int i = tid + it * 256;
            int r = i >> 2, pc = i & 3;
            uint32_t d = (uint32_t)(r * RS2 + pc * 16);
            size_t aoff = (size_t)(row0 + r) * K + kOff + pc * 8;
            cpa16(s0 + ST_AHI + d, Ahi + aoff);
            cpa16(s0 + ST_ALO + d, Alo + aoff);
            size_t boff = (size_t)(col0 + r) * K + kOff + pc * 8;
            cpa16(s0 + ST_BHI + d, Bhi + boff);
            cpa16(s0 + ST_BLO + d, Blo + boff);
        }
    };

    issue(0, 0);
    asm volatile("cp.async.commit_group;" ::: "memory");

    const uint32_t a_lane = (uint32_t)((lane & 15) * RS2 + ((lane >> 4) & 1) * 16);
    const uint32_t b_lane = (uint32_t)((((lane >> 4) & 1) * 8 + (lane & 7)) * RS2 + ((lane >> 3) & 1) * 16);

    for (int kc = 0; kc < nc; kc++) {
        if (kc + 1 < nc) issue(kc + 1, (kc + 1) & 1);
        asm volatile("cp.async.commit_group;" ::: "memory");
        asm volatile("cp.async.wait_group 1;" ::: "memory");
        __syncthreads();
        const uint32_t st = sb + (kc & 1) * ST_SZ;
#pragma unroll
        for (int ks = 0; ks < 2; ks++) {
            const uint32_t kso = (uint32_t)(ks * 32);
            uint32_t ah[2][4], al[2][4];
#pragma unroll
            for (int mt = 0; mt < 2; mt++) {
                uint32_t ra = st + ST_AHI + (uint32_t)((wr + mt * 16) * RS2) + a_lane + kso;
                ldsm4(ah[mt], ra);
                ldsm4(al[mt], ra + (ST_ALO - ST_AHI));
            }
#pragma unroll
            for (int ntp = 0; ntp < 4; ntp++) {
                uint32_t rb = st + ST_BHI + (uint32_t)((wc + ntp * 16) * RS2) + b_lane + kso;
                uint32_t bh[4], bl[4];
                ldsm4(bh, rb);
                ldsm4(bl, rb + (ST_BLO - ST_BHI));
#pragma unroll
                for (int mt = 0; mt < 2; mt++) {
                    float* ce = acc[mt * 8 + ntp * 2];
                    mma16816(ce, ah[mt], bh[0], bh[1]);
                    mma16816(ce, ah[mt], bl[0], bl[1]);
                    mma16816(ce, al[mt], bh[0], bh[1]);
                    float* co = acc[mt * 8 + ntp * 2 + 1];
                    mma16816(co, ah[mt], bh[2], bh[3]);
                    mma16816(co, ah[mt], bl[2], bl[3]);
                    mma16816(co, al[mt], bh[2], bh[3]);
                }
            }
        }
        __syncthreads();
    }

    // ---- epilogue ----
#pragma unroll
    for (int mt = 0; mt < 2; mt++) {
#pragma unroll
        for (int nt = 0; nt < 8; nt++) {
            const float* c = acc[mt * 8 + nt];
            int col = col0 + wc + nt * 8 + lq * 2;
            float b0 = bias[col], b1 = bias[col + 1];
            int r0 = row0 + wr + mt * 16 + lr;
            int r1 = r0 + 8;
            float2 o;
            uint32_t h, l;
            if (r0 < n) {
                o.x = c[0] + b0; o.y = c[1] + b1;
                if (relu) { o.x = fmaxf(o.x, 0.f); o.y = fmaxf(o.y, 0.f); }
                *(float2*)&C[(size_t)r0 * ldc + col] = o;
                if (wsplit) {
                    split2(o.x, o.y, h, l);
                    Chi[(size_t)r0 * 128 + (col >> 1)] = h;
                    Clo[(size_t)r0 * 128 + (col >> 1)] = l;
                }
            }
            if (r1 < n) {
                o.x = c[2] + b0; o.y = c[3] + b1;
                if (relu) { o.x = fmaxf(o.x, 0.f); o.y = fmaxf(o.y, 0.f); }
                *(float2*)&C[(size_t)r1 * ldc + col] = o;
                if (wsplit) {
                    split2(o.x, o.y, h, l);
                    Chi[(size_t)r1 * 128 + (col >> 1)] = h;
                    Clo[(size_t)r1 * 128 + (col >> 1)] = l;
                }
            }
        }
    }
}

// ---------------- init: zero degrees + index width detection ----------------
__global__ void init_deg_kernel(const void* ei) {
    int i = blockIdx.x * blockDim.x + threadIdx.x;
    if (i < Nn) g_deg[i] = 0;
    if (i == 0) {
        const long long* p = (const long long*)ei;
        int ok = 1;
        for (int k = 0; k < 64; k++) {
            long long v = p[k];
            if (v < 0 || v >= Nn) { ok = 0; break; }
        }
        g_idx64 = ok;
    }
}

__global__ void convert_count_kernel(const void* ei) {
    int m = blockIdx.x * blockDim.x + threadIdx.x;
    if (m >= Mm) return;
    int is64 = g_idx64;
    int s, d;
    if (m < Ee) {
        if (is64) { s = (int)((const long long*)ei)[m]; d = (int)((const long long*)ei)[(long long)Ee + m]; }
        else      { s = ((const int*)ei)[m];            d = ((const int*)ei)[Ee + m]; }
    } else { s = d = m - Ee; }
    g_src[m] = s;
    g_dst[m] = d;
    atomicAdd(&g_deg[d], 1);
}

__global__ void scan1_kernel() {
    __shared__ int smi[SCANB];
    int i = blockIdx.x * SCANB + threadIdx.x;
    int v = (i < Nn) ? g_deg[i] : 0;
    smi[threadIdx.x] = v;
    __syncthreads();
    for (int o = 1; o < SCANB; o <<= 1) {
        int t = (threadIdx.x >= o) ? smi[threadIdx.x - o] : 0;
        __syncthreads();
        smi[threadIdx.x] += t;
        __syncthreads();
    }
    if (i < Nn) g_incl[i] = smi[threadIdx.x];
    if (threadIdx.x == SCANB - 1) g_bsum[blockIdx.x] = smi[SCANB - 1];
}

__global__ void scan2_kernel() {
    __shared__ int smi[64];
    int t = threadIdx.x;
    int v = (t < NSCANB) ? g_bsum[t] : 0;
    smi[t] = v;
    __syncthreads();
    for (int o = 1; o < 64; o <<= 1) {
        int u = (t >= o) ? smi[t - o] : 0;
        __syncthreads();
        smi[t] += u;
        __syncthreads();
    }
    if (t < NSCANB) g_bsum[t] = smi[t];
}

__global__ void scan3_kernel() {
    int i = blockIdx.x * blockDim.x + threadIdx.x;
    if (i >= Nn) return;
    int b = i >> 10;
    int excl = g_incl[i] - g_deg[i] + (b ? g_bsum[b - 1] : 0);
    g_rowptr[i] = excl;
    g_cursor[i] = excl;
    if (i == 0) g_rowptr[Nn] = Mm;
}

__global__ void csr_fill_kernel() {
    int m = blockIdx.x * blockDim.x + threadIdx.x;
    if (m >= Mm) return;
    int d = g_dst[m];
    int pos = atomicAdd(&g_cursor[d], 1);
    g_csrsrc[pos] = g_src[m];
}

// ---------------- fused edge phase (warp/dst) on interleaved xlr[N][512] ------------
__global__ __launch_bounds__(256)
void edge_fused_kernel(const int* __restrict__ rowptr, const int* __restrict__ csrsrc,
                       const float4* __restrict__ xlr,
                       const float4* __restrict__ att4,
                       const float4* __restrict__ bias_c4,
                       const float4* __restrict__ lg4, const float4* __restrict__ lb4,
                       float4* __restrict__ x,
                       uint32_t* __restrict__ xhi32, uint32_t* __restrict__ xlo32) {
    int d = (blockIdx.x * blockDim.x + threadIdx.x) >> 5;
    int lane = threadIdx.x & 31;
    if (d >= Nn) return;

    float4 r0 = xlr[(size_t)d * 128 + 64 + lane];   // xr = cols 256..511
    float4 r1 = xlr[(size_t)d * 128 + 96 + lane];
    float4 t0 = att4[lane];
    float4 t1 = att4[32 + lane];

    float m = -INFINITY, s = 0.f;
    float4 acc0 = make_float4(0,0,0,0), acc1 = make_float4(0,0,0,0);

    int p0 = rowptr[d], p1 = rowptr[d + 1];
    int p = p0;
    for (; p + 1 < p1; p += 2) {
        int sa = csrsrc[p], sb2 = csrsrc[p + 1];
        float4 c0 = xlr[(size_t)sa * 128 + lane];
        float4 c1 = xlr[(size_t)sa * 128 + 32 + lane];
        float4 d0 = xlr[(size_t)sb2 * 128 + lane];
        float4 d1 = xlr[(size_t)sb2 * 128 + 32 + lane];
        float e1 = 0.f, e2 = 0.f, v;
        v = c0.x + r0.x; v = (v > 0.f) ? v : 0.2f * v; e1 = fmaf(v, t0.x, e1);
        v = d0.x + r0.x; v = (v > 0.f) ? v : 0.2f * v; e2 = fmaf(v, t0.x, e2);
        v = c0.y + r0.y; v = (v > 0.f) ? v : 0.2f * v; e1 = fmaf(v, t0.y, e1);
        v = d0.y + r0.y; v = (v > 0.f) ? v : 0.2f * v; e2 = fmaf(v, t0.y, e2);
        v = c0.z + r0.z; v = (v > 0.f) ? v : 0.2f * v; e1 = fmaf(v, t0.z, e1);
        v = d0.z + r0.z; v = (v > 0.f) ? v : 0.2f * v; e2 = fmaf(v, t0.z, e2);
        v = c0.w + r0.w; v = (v > 0.f) ? v : 0.2f * v; e1 = fmaf(v, t0.w, e1);
        v = d0.w + r0.w; v = (v > 0.f) ? v : 0.2f * v; e2 = fmaf(v, t0.w, e2);
        v = c1.x + r1.x; v = (v > 0.f) ? v : 0.2f * v; e1 = fmaf(v, t1.x, e1);
        v = d1.x + r1.x; v = (v > 0.f) ? v : 0.2f * v; e2 = fmaf(v, t1.x, e2);
        v = c1.y + r1.y; v = (v > 0.f) ? v : 0.2f * v; e1 = fmaf(v, t1.y, e1);
        v = d1.y + r1.y; v = (v > 0.f) ? v : 0.2f * v; e2 = fmaf(v, t1.y, e2);
        v = c1.z + r1.z; v = (v > 0.f) ? v : 0.2f * v; e1 = fmaf(v, t1.z, e1);
        v = d1.z + r1.z; v = (v > 0.f) ? v : 0.2f * v; e2 = fmaf(v, t1.z, e2);
        v = c1.w + r1.w; v = (v > 0.f) ? v : 0.2f * v; e1 = fmaf(v, t1.w, e1);
        v = d1.w + r1.w; v = (v > 0.f) ? v : 0.2f * v; e2 = fmaf(v, t1.w, e2);
#pragma unroll
        for (int o = 16; o; o >>= 1) {
            e1 += __shfl_xor_sync(0xffffffffu, e1, o);
            e2 += __shfl_xor_sync(0xffffffffu, e2, o);
        }
        float mn = fmaxf(m, fmaxf(e1, e2));
        float cc = __expf(m - mn);
        float w1 = __expf(e1 - mn);
        float w2 = __expf(e2 - mn);
        s = s * cc + w1 + w2;
        acc0.x = acc0.x * cc + w1 * c0.x + w2 * d0.x;
        acc0.y = acc0.y * cc + w1 * c0.y + w2 * d0.y;
        acc0.z = acc0.z * cc + w1 * c0.z + w2 * d0.z;
        acc0.w = acc0.w * cc + w1 * c0.w + w2 * d0.w;
        acc1.x = acc1.x * cc + w1 * c1.x + w2 * d1.x;
        acc1.y = acc1.y * cc + w1 * c1.y + w2 * d1.y;
        acc1.z = acc1.z * cc + w1 * c1.z + w2 * d1.z;
        acc1.w = acc1.w * cc + w1 * c1.w + w2 * d1.w;
        m = mn;
    }
    if (p < p1) {
        int sa = csrsrc[p];
        float4 c0 = xlr[(size_t)sa * 128 + lane];
        float4 c1 = xlr[(size_t)sa * 128 + 32 + lane];
        float e = 0.f, v;
        v = c0.x + r0.x; v = (v > 0.f) ? v : 0.2f * v; e = fmaf(v, t0.x, e);
        v = c0.y + r0.y; v = (v > 0.f) ? v : 0.2f * v; e = fmaf(v, t0.y, e);
        v = c0.z + r0.z; v = (v > 0.f) ? v : 0.2f * v; e = fmaf(v, t0.z, e);
        v = c0.w + r0.w; v = (v > 0.f) ? v : 0.2f * v; e = fmaf(v, t0.w, e);
        v = c1.x + r1.x; v = (v > 0.f) ? v : 0.2f * v; e = fmaf(v, t1.x, e);
        v = c1.y + r1.y; v = (v > 0.f) ? v : 0.2f * v; e = fmaf(v, t1.y, e);
        v = c1.z + r1.z; v = (v > 0.f) ? v : 0.2f * v; e = fmaf(v, t1.z, e);
        v = c1.w + r1.w; v = (v > 0.f) ? v : 0.2f * v; e = fmaf(v, t1.w, e);
#pragma unroll
        for (int o = 16; o; o >>= 1) e += __shfl_xor_sync(0xffffffffu, e, o);
        float mn = fmaxf(m, e);
        float cc = __expf(m - mn);
        float w = __expf(e - mn);
        s = s * cc + w;
        acc0.x = acc0.x * cc + w * c0.x; acc0.y = acc0.y * cc + w * c0.y;
        acc0.z = acc0.z * cc + w * c0.z; acc0.w = acc0.w * cc + w * c0.w;
        acc1.x = acc1.x * cc + w * c1.x; acc1.y = acc1.y * cc + w * c1.y;
        acc1.z = acc1.z * cc + w * c1.z; acc1.w = acc1.w * cc + w * c1.w;
        m = mn;
    }

    float inv = 1.f / s;
    float4 bc0 = bias_c4[lane], bc1 = bias_c4[32 + lane];
    float v0x = acc0.x * inv + bc0.x, v0y = acc0.y * inv + bc0.y;
    float v0z = acc0.z * inv + bc0.z, v0w = acc0.w * inv + bc0.w;
    float v1x = acc1.x * inv + bc1.x, v1y = acc1.y * inv + bc1.y;
    float v1z = acc1.z * inv + bc1.z, v1w = acc1.w * inv + bc1.w;

    float sum = v0x + v0y + v0z + v0w + v1x + v1y + v1z + v1w;
#pragma unroll
    for (int o = 16; o; o >>= 1) sum += __shfl_xor_sync(0xffffffffu, sum, o);
    float mu = sum * (1.f / Hh);
    float d0x = v0x - mu, d0y = v0y - mu, d0z = v0z - mu, d0w = v0w - mu;
    float d1x = v1x - mu, d1y = v1y - mu, d1z = v1z - mu, d1w = v1w - mu;
    float vsum = d0x*d0x + d0y*d0y + d0z*d0z + d0w*d0w + d1x*d1x + d1y*d1y + d1z*d1z + d1w*d1w;
#pragma unroll
    for (int o = 16; o; o >>= 1) vsum += __shfl_xor_sync(0xffffffffu, vsum, o);
    float rs = rsqrtf(vsum * (1.f / Hh) + 1e-5f);

    float4 lg0 = lg4[lane], lg1 = lg4[32 + lane];
    float4 lb0 = lb4[lane], lb1 = lb4[32 + lane];
    float4 xr0 = x[(size_t)d * 64 + lane];
    float4 xr1 = x[(size_t)d * 64 + 32 + lane];
    float4 o0, o1;
    o0.x = fmaxf(d0x * rs * lg0.x + lb0.x, 0.f) + xr0.x;
    o0.y = fmaxf(d0y * rs * lg0.y + lb0.y, 0.f) + xr0.y;
    o0.z = fmaxf(d0z * rs * lg0.z + lb0.z, 0.f) + xr0.z;
    o0.w = fmaxf(d0w * rs * lg0.w + lb0.w, 0.f) + xr0.w;
    o1.x = fmaxf(d1x * rs * lg1.x + lb1.x, 0.f) + xr1.x;
    o1.y = fmaxf(d1y * rs * lg1.y + lb1.y, 0.f) + xr1.y;
    o1.z = fmaxf(d1z * rs * lg1.z + lb1.z, 0.f) + xr1.z;
    o1.w = fmaxf(d1w * rs * lg1.w + lb1.w, 0.f) + xr1.w;
    x[(size_t)d * 64 + lane] = o0;
    x[(size_t)d * 64 + 32 + lane] = o1;

    size_t b32 = (size_t)d * 128 + 2 * lane;
    uint32_t h, l;
    split2(o0.x, o0.y, h, l); xhi32[b32]      = h; xlo32[b32]      = l;
    split2(o0.z, o0.w, h, l); xhi32[b32 + 1]  = h; xlo32[b32 + 1]  = l;
    split2(o1.x, o1.y, h, l); xhi32[b32 + 64] = h; xlo32[b32 + 64] = l;
    split2(o1.z, o1.w, h, l); xhi32[b32 + 65] = h; xlo32[b32 + 65] = l;
}

// ---------------- gate dot ----------------
__global__ void gate_dot_kernel(const float4* __restrict__ hid, const float4* __restrict__ Wg2,
                                const float* __restrict__ bg2, float* __restrict__ gate) {
    int w = (blockIdx.x * blockDim.x + threadIdx.x) >> 5;
    int lane = threadIdx.x & 31;
    if (w >= Nn) return;
    const float4* p = hid + (size_t)w * 64;
    float sum = 0.f;
#pragma unroll
    for (int j = lane; j < 64; j += 32) {
        float4 a = p[j], t = Wg2[j];
        sum = fmaf(a.x, t.x, fmaf(a.y, t.y, fmaf(a.z, t.z, fmaf(a.w, t.w, sum))));
    }
#pragma unroll
    for (int o = 16; o; o >>= 1) sum += __shfl_xor_sync(0xffffffffu, sum, o);
    if (lane == 0) gate[w] = sum + bg2[0];
}

// ---------------- batch segment boundaries ----------------
__global__ void bstart_kernel(const void* __restrict__ batch) {
    int g = threadIdx.x;
    if (g > Gg) return;
    if (g == Gg) { g_bstart[Gg] = Nn; return; }
    int is64 = g_idx64;
    int lo = 0, hi = Nn;
    while (lo < hi) {
        int mid = (lo + hi) >> 1;
        long long v = is64 ? ((const long long*)batch)[mid] : (long long)((const int*)batch)[mid];
        if (v < g) lo = mid + 1; else hi = mid;
    }
    g_bstart[g] = lo;
}

// ---------------- segmented softmax pooling ----------------
__global__ __launch_bounds__(256)
void segpool_kernel(const float* __restrict__ gate, const float* __restrict__ x,
                    float* __restrict__ pooled) {
    int g = blockIdx.x, tid = threadIdx.x;
    int s = g_bstart[g], e = g_bstart[g + 1];
    __shared__ float red[8];
    __shared__ float ws[256];
    if (s >= e) { pooled[(size_t)g * Hh + tid] = 0.f; return; }

    float m = -INFINITY;
    for (int i = s + tid; i < e; i += 256) m = fmaxf(m, gate[i]);
#pragma unroll
    for (int o = 16; o; o >>= 1) m = fmaxf(m, __shfl_xor_sync(0xffffffffu, m, o));
    if ((tid & 31) == 0) red[tid >> 5] = m;
    __syncthreads();
    m = fmaxf(fmaxf(fmaxf(red[0], red[1]), fmaxf(red[2], red[3])),
              fmaxf(fmaxf(red[4], red[5]), fmaxf(red[6], red[7])));
    __syncthreads();

    float sum = 0.f;
    for (int i = s + tid; i < e; i += 256) sum += __expf(gate[i] - m);
#pragma unroll
    for (int o = 16; o; o >>= 1) sum += __shfl_xor_sync(0xffffffffu, sum, o);
    if ((tid & 31) == 0) red[tid >> 5] = sum;
    __syncthreads();
    sum = red[0] + red[1] + red[2] + red[3] + red[4] + red[5] + red[6] + red[7];
    __syncthreads();

    float acc = 0.f;
    for (int i0 = s; i0 < e; i0 += 256) {
        int n = min(256, e - i0);
        if (tid < n) ws[tid] = __expf(gate[i0 + tid] - m);
        __syncthreads();
        for (int j = 0; j < n; j++) acc = fmaf(ws[j], x[(size_t)(i0 + j) * Hh + tid], acc);
        __syncthreads();
    }
    pooled[(size_t)g * Hh + tid] = acc / sum;
}

// ---------------- head ----------------
__global__ void head_kernel(const float* __restrict__ pooled,
                            const float* __restrict__ Ws, const float* __restrict__ bs,
                            const float* __restrict__ Wc, const float* __restrict__ bc,
                            const float* __restrict__ Wr1, const float* __restrict__ br1,
                            const float* __restrict__ Wr2, const float* __restrict__ br2,
                            float* __restrict__ out) {
    int g = blockIdx.x, t = threadIdx.x;
    __shared__ float sp[Hh];
    __shared__ float sz[Hh];
    __shared__ float sr[128];
    sp[t] = pooled[(size_t)g * Hh + t];
    __syncthreads();
    float acc = bs[t];
#pragma unroll 8
    for (int k = 0; k < Hh; k++) acc = fmaf(sp[k], Ws[(size_t)t * Hh + k], acc);
    sz[t] = fmaxf(acc, 0.f);
    __syncthreads();
    if (t < NBc) {
        float a2 = bc[t];
#pragma unroll 8
        for (int k = 0; k < Hh; k++) a2 = fmaf(sz[k], Wc[(size_t)t * Hh + k], a2);
        out[(size_t)g * NBc + t] = a2;
    }
    if (t < 128) {
        float a3 = br1[t];
#pragma unroll 8
        for (int k = 0; k < Hh; k++) a3 = fmaf(sz[k], Wr1[(size_t)t * Hh + k], a3);
        sr[t] = fmaxf(a3, 0.f);
    }
    __syncthreads();
    if (t < 128) {
        float v = sr[t] * Wr2[t];
#pragma unroll
        for (int o = 16; o; o >>= 1) v += __shfl_xor_sync(0xffffffffu, v, o);
        if ((t & 31) == 0) sp[t >> 5] = v;
    }
    __syncthreads();
    if (t == 0) {
        float tot = sp[0] + sp[1] + sp[2] + sp[3] + br2[0];
        out[(size_t)Gg * NBc + g] = tanhf(tot);
    }
}

// ---------------- launch ----------------
extern "C" void kernel_launch(void* const* d_in, const int* in_sizes, int n_in,
                              void* d_out, int out_size) {
    const float* x_in   = (const float*)d_in[0];
    const void*  ei     = d_in[1];
    const void*  batch  = d_in[2];
    const float* W_in   = (const float*)d_in[3];
    const float* b_in   = (const float*)d_in[4];
    const float* Wl     = (const float*)d_in[5];
    const float* bl     = (const float*)d_in[6];
    const float* Wr     = (const float*)d_in[7];
    const float* br     = (const float*)d_in[8];
    const float* att    = (const float*)d_in[9];
    const float* bias_c = (const float*)d_in[10];
    const float* ln_g   = (const float*)d_in[11];
    const float* ln_b   = (const float*)d_in[12];
    const float* Wg1    = (const float*)d_in[13];
    const float* bg1    = (const float*)d_in[14];
    const float* Wg2    = (const float*)d_in[15];
    const float* bg2    = (const float*)d_in[16];
    const float* Ws     = (const float*)d_in[17];
    const float* bs     = (const float*)d_in[18];
    const float* Wc     = (const float*)d_in[19];
    const float* bc     = (const float*)d_in[20];
    const float* Wr1    = (const float*)d_in[21];
    const float* br1    = (const float*)d_in[22];
    const float* Wr2    = (const float*)d_in[23];
    const float* br2    = (const float*)d_in[24];
    float* out = (float*)d_out;

    float *px, *pxlr, *pxl, *pgate, *ppooled, *pbiascat;
    __nv_bfloat16 *pxhi, *pxlo, *pxinhi, *pxinlo, *pwhi, *pwlo;
    int *prowptr, *pcsrsrc;
    cudaGetSymbolAddress((void**)&px,      g_x);
    cudaGetSymbolAddress((void**)&pxlr,    g_xlr);
    cudaGetSymbolAddress((void**)&pxl,     g_xl);
    cudaGetSymbolAddress((void**)&pxhi,    g_xhi);
    cudaGetSymbolAddress((void**)&pxlo,    g_xlo);
    cudaGetSymbolAddress((void**)&pxinhi,  g_xinhi);
    cudaGetSymbolAddress((void**)&pxinlo,  g_xinlo);
    cudaGetSymbolAddress((void**)&pwhi,    g_whi);
    cudaGetSymbolAddress((void**)&pwlo,    g_wlo);
    cudaGetSymbolAddress((void**)&pbiascat,g_biascat);
    cudaGetSymbolAddress((void**)&pgate,   g_gate);
    cudaGetSymbolAddress((void**)&ppooled, g_pooled);
    cudaGetSymbolAddress((void**)&prowptr, g_rowptr);
    cudaGetSymbolAddress((void**)&pcsrsrc, g_csrsrc);

    cudaFuncSetAttribute(gemm_bf16_kernel, cudaFuncAttributeMaxDynamicSharedMemorySize, GSM_TOT);

    const dim3 proj_grid(2, (Nn + 127) / 128);
    const dim3 fused_grid(4, (Nn + 127) / 128);
    const int NODE_W_BLOCKS = (Nn * 32 + 255) / 256;

    // ---- weight + input splits ----
    split_pairs_kernel<<<(16384/2 + 255)/256, 256>>>((const float2*)W_in,
        (uint32_t*)(pwhi + WOFF_IN), (uint32_t*)(pwlo + WOFF_IN), 16384/2);
    split_wcat_kernel<<<(Ll*512*128 + 255)/256, 256>>>((const float2*)Wl, (const float2*)Wr,
        (uint32_t*)(pwhi + WOFF_LR), (uint32_t*)(pwlo + WOFF_LR));
    split_pairs_kernel<<<(65536/2 + 255)/256, 256>>>((const float2*)Wg1,
        (uint32_t*)(pwhi + WOFF_G1), (uint32_t*)(pwlo + WOFF_G1), 65536/2);
    split_xin_kernel<<<(NPAD*(IND/2) + 255)/256, 256>>>((const float2*)x_in,
        (uint32_t*)pxinhi, (uint32_t*)pxinlo);
    biascat_kernel<<<(Ll*512 + 255)/256, 256>>>(bl, br);

    // ---- CSR build ----
    init_deg_kernel<<<(Nn + 255) / 256, 256>>>(ei);
    convert_count_kernel<<<(Mm + 255) / 256, 256>>>(ei);
    scan1_kernel<<<NSCANB, SCANB>>>();
    scan2_kernel<<<1, 64>>>();
    scan3_kernel<<<(Nn + 255) / 256, 256>>>();
    csr_fill_kernel<<<(Mm + 255) / 256, 256>>>();
    bstart_kernel<<<1, Gg + 1>>>(batch);

    // ---- input projection (K=64) ----
    gemm_bf16_kernel<<<proj_grid, 256, GSM_TOT>>>(pxinhi, pxinlo,
        pwhi + WOFF_IN, pwlo + WOFF_IN, b_in, px, Hh,
        (uint32_t*)pxhi, (uint32_t*)pxlo, 1, Nn, IND, 0);

    // ---- GAT layers: one fused N=512 GEMM per layer ----
    for (int l = 0; l < Ll; l++) {
        gemm_bf16_kernel<<<fused_grid, 256, GSM_TOT>>>(pxhi, pxlo,
            pwhi + WOFF_LR + (size_t)l * 512 * Hh, pwlo + WOFF_LR + (size_t)l * 512 * Hh,
            pbiascat + l * 512, pxlr, 512, nullptr, nullptr, 0, Nn, Hh, 0);
        edge_fused_kernel<<<NODE_W_BLOCKS, 256>>>(prowptr, pcsrsrc,
            (const float4*)pxlr,
            (const float4*)(att + l * Hh),
            (const float4*)(bias_c + l * Hh),
            (const float4*)(ln_g + l * Hh), (const float4*)(ln_b + l * Hh),
            (float4*)px, (uint32_t*)pxhi, (uint32_t*)pxlo);
    }

    // ---- readout ----
    gemm_bf16_kernel<<<proj_grid, 256, GSM_TOT>>>(pxhi, pxlo,
        pwhi + WOFF_G1, pwlo + WOFF_G1, bg1, pxl, Hh, nullptr, nullptr, 0, Nn, Hh, 1);
    gate_dot_kernel<<<NODE_W_BLOCKS, 256>>>((const float4*)pxl, (const float4*)Wg2, bg2, pgate);
    segpool_kernel<<<Gg, 256>>>(pgate, px, ppooled);
    head_kernel<<<Gg, Hh>>>(ppooled, Ws, bs, Wc, bc, Wr1, br1, Wr2, br2, out);
}

// round 17
// speedup vs baseline: 1.2945x; 1.1797x over previous
#include <cuda_runtime.h>
#include <cuda_fp16.h>
#include <math.h>
#include <stdint.h>

#define Nn 50000
#define Ee 300000
#define Mm (Ee + Nn)
#define NPAD 50048          // Nn rounded up to 128
#define IND 64
#define Hh 256
#define Ll 4
#define NBc 181
#define Gg 64
#define SCANB 1024
#define NSCANB ((Nn + SCANB - 1) / SCANB)

// weight split offsets (elements)
#define WOFF_IN  0
#define WOFF_LR  16384
#define WOFF_G1  (16384 + 4 * 512 * 256)
#define WTOT     (16384 + 4 * 512 * 256 + 65536)

// ---------------- scratch (device globals; no allocation allowed) ----------------
__device__ float g_x[Nn * Hh];
__device__ float g_xlr[Nn * 512];       // fused xl|xr per node
__device__ float g_xl[Nn * Hh];         // gate hidden
__device__ __align__(16) __half g_xh[NPAD * Hh];     // fp16 activations (GEMM A operand)
__device__ __align__(16) __half g_xinh[NPAD * IND];
__device__ __align__(16) __half g_whi[WTOT];
__device__ __align__(16) __half g_wlo[WTOT];
__device__ float g_biascat[Ll * 512];
__device__ float g_gate[Nn];
__device__ float g_pooled[Gg * Hh];
__device__ int   g_src[Mm];
__device__ int   g_dst[Mm];
__device__ int   g_deg[Nn];
__device__ int   g_incl[Nn];
__device__ int   g_bsum[NSCANB];
__device__ int   g_rowptr[Nn + 1];
__device__ int   g_cursor[Nn];
__device__ int   g_csrsrc[Mm];
__device__ int   g_bstart[Gg + 1];
__device__ int   g_idx64;

// ---------------- helpers ----------------
__device__ __forceinline__ uint32_t smem_to_u32(const void* smem_ptr) {
    uint32_t addr;
    asm("{ .reg .u64 tmp; cvta.to.shared.u64 tmp, %1; cvt.u32.u64 %0, tmp; }"
        : "=r"(addr) : "l"(smem_ptr));
    return addr;
}

__device__ __forceinline__ void cpa16(uint32_t dst, const void* src) {
    asm volatile("cp.async.cg.shared.global [%0], [%1], 16;" :: "r"(dst), "l"(src));
}

__device__ __forceinline__ void ldsm4(uint32_t* r, uint32_t addr) {
    asm volatile("ldmatrix.sync.aligned.m8n8.x4.shared.b16 {%0,%1,%2,%3}, [%4];"
        : "=r"(r[0]), "=r"(r[1]), "=r"(r[2]), "=r"(r[3]) : "r"(addr));
}

// fp16 weight split: hi = fp16(x), lo = fp16(x - hi)
__device__ __forceinline__ void split2h(float x, float y, uint32_t& hi, uint32_t& lo) {
    __half hx = __float2half_rn(x);
    __half hy = __float2half_rn(y);
    __half lx = __float2half_rn(x - __half2float(hx));
    __half ly = __float2half_rn(y - __half2float(hy));
    hi = ((uint32_t)__half_as_ushort(hy) << 16) | __half_as_ushort(hx);
    lo = ((uint32_t)__half_as_ushort(ly) << 16) | __half_as_ushort(lx);
}

__device__ __forceinline__ uint32_t pack_h2(float x, float y) {
    __half2 h = __floats2half2_rn(x, y);
    return *(uint32_t*)&h;
}

__device__ __forceinline__ void mma16816(float* c, const uint32_t* a, uint32_t b0, uint32_t b1) {
    asm volatile(
        "mma.sync.aligned.m16n8k16.row.col.f32.f16.f16.f32 "
        "{%0,%1,%2,%3}, {%4,%5,%6,%7}, {%8,%9}, {%0,%1,%2,%3};"
        : "+f"(c[0]), "+f"(c[1]), "+f"(c[2]), "+f"(c[3])
        : "r"(a[0]), "r"(a[1]), "r"(a[2]), "r"(a[3]), "r"(b0), "r"(b1));
}

// ---------------- split kernels ----------------
__global__ void split_pairs_kernel(const float2* __restrict__ src,
                                   uint32_t* __restrict__ dhi, uint32_t* __restrict__ dlo, int n2) {
    int i = blockIdx.x * blockDim.x + threadIdx.x;
    if (i >= n2) return;
    float2 v = src[i];
    uint32_t h, l;
    split2h(v.x, v.y, h, l);
    dhi[i] = h; dlo[i] = l;
}

// concatenated [L][512][256] from Wl [L][256][256] + Wr [L][256][256]
__global__ void split_wcat_kernel(const float2* __restrict__ Wl, const float2* __restrict__ Wr,
                                  uint32_t* __restrict__ dhi, uint32_t* __restrict__ dlo) {
    int i = blockIdx.x * blockDim.x + threadIdx.x;
    if (i >= Ll * 512 * 128) return;
    int l = i / (512 * 128);
    int rem = i - l * 512 * 128;
    int r = rem >> 7, c2 = rem & 127;
    float2 v = (r < 256) ? Wl[((size_t)l * 256 + r) * 128 + c2]
                         : Wr[((size_t)l * 256 + (r - 256)) * 128 + c2];
    uint32_t h, lo;
    split2h(v.x, v.y, h, lo);
    dhi[i] = h; dlo[i] = lo;
}

__global__ void biascat_kernel(const float* __restrict__ bl, const float* __restrict__ br) {
    int i = blockIdx.x * blockDim.x + threadIdx.x;
    if (i >= Ll * 512) return;
    int l = i >> 9, c = i & 511;
    g_biascat[i] = (c < 256) ? bl[l * 256 + c] : br[l * 256 + c - 256];
}

__global__ void conv_xin_kernel(const float2* __restrict__ src, uint32_t* __restrict__ dh) {
    int i = blockIdx.x * blockDim.x + threadIdx.x;
    if (i >= NPAD * (IND / 2)) return;
    float2 v = (i < Nn * (IND / 2)) ? src[i] : make_float2(0.f, 0.f);
    dh[i] = pack_h2(v.x, v.y);
}

// ---------------- fp16 2-term pipelined tensor GEMM ----------------
// C[n,N] = A[n,K] @ W[N,K]^T + bias ; A fp16, W split fp16 hi/lo.
// CTA 128x128, 8 warps (4x2), warp tile 32x64, K-chunk 32, 2-stage cp.async.
#define RS2 80
#define ST_A   0
#define ST_BHI 10240
#define ST_BLO 20480
#define ST_SZ  30720
#define GSM_TOT (2 * ST_SZ)

__global__ __launch_bounds__(256, 2)
void gemm_fp16_kernel(const __half* __restrict__ Ah,
                      const __half* __restrict__ Bhi, const __half* __restrict__ Blo,
                      const float* __restrict__ bias, float* __restrict__ C, int ldc,
                      uint32_t* __restrict__ Ch, int wh, int n, int K, int relu) {
    extern __shared__ char smc[];
    uint32_t sb = smem_to_u32(smc);
    const int tid = threadIdx.x;
    const int wid = tid >> 5, lane = tid & 31;
    const int row0 = blockIdx.y * 128;
    const int col0 = blockIdx.x * 128;
    const int wr = (wid & 3) * 32;
    const int wc = (wid >> 2) * 64;
    const int lr = lane >> 2;
    const int lq = lane & 3;

    float acc[16][4];
#pragma unroll
    for (int t = 0; t < 16; t++)
#pragma unroll
        for (int q = 0; q < 4; q++) acc[t][q] = 0.f;

    const int nc = K >> 5;

    auto issue = [&](int kc, int stage) {
        const int kOff = kc * 32;
        const uint32_t s0 = sb + stage * ST_SZ;
#pragma unroll
        for (int it = 0; it < 2; it++) {
            int i = tid + it * 256;
            int r = i >> 2, pc = i & 3;
            uint32_t d = (uint32_t)(r * RS2 + pc * 16);
            size_t aoff = (size_t)(row0 + r) * K + kOff + pc * 8;
            cpa16(s0 + ST_A + d, Ah + aoff);
            size_t boff = (size_t)(col0 + r) * K + kOff + pc * 8;
            cpa16(s0 + ST_BHI + d, Bhi + boff);
            cpa16(s0 + ST_BLO + d, Blo + boff);
        }
    };

    issue(0, 0);
    asm volatile("cp.async.commit_group;" ::: "memory");

    const uint32_t a_lane = (uint32_t)((lane & 15) * RS2 + ((lane >> 4) & 1) * 16);
    const uint32_t b_lane = (uint32_t)((((lane >> 4) & 1) * 8 + (lane & 7)) * RS2 + ((lane >> 3) & 1) * 16);

    for (int kc = 0; kc < nc; kc++) {
        if (kc + 1 < nc) issue(kc + 1, (kc + 1) & 1);
        asm volatile("cp.async.commit_group;" ::: "memory");
        asm volatile("cp.async.wait_group 1;" ::: "memory");
        __syncthreads();
        const uint32_t st = sb + (kc & 1) * ST_SZ;
#pragma unroll
        for (int ks = 0; ks < 2; ks++) {
            const uint32_t kso = (uint32_t)(ks * 32);
            uint32_t ah[2][4];
#pragma unroll
            for (int mt = 0; mt < 2; mt++) {
                uint32_t ra = st + ST_A + (uint32_t)((wr + mt * 16) * RS2) + a_lane + kso;
                ldsm4(ah[mt], ra);
            }
#pragma unroll
            for (int ntp = 0; ntp < 4; ntp++) {
                uint32_t rb = st + ST_BHI + (uint32_t)((wc + ntp * 16) * RS2) + b_lane + kso;
                uint32_t bh[4], bl[4];
                ldsm4(bh, rb);
                ldsm4(bl, rb + (ST_BLO - ST_BHI));
#pragma unroll
                for (int mt = 0; mt < 2; mt++) {
                    float* ce = acc[mt * 8 + ntp * 2];
                    mma16816(ce, ah[mt], bh[0], bh[1]);
                    mma16816(ce, ah[mt], bl[0], bl[1]);
                    float* co = acc[mt * 8 + ntp * 2 + 1];
                    mma16816(co, ah[mt], bh[2], bh[3]);
                    mma16816(co, ah[mt], bl[2], bl[3]);
                }
            }
        }
        __syncthreads();
    }

    // ---- epilogue ----
#pragma unroll
    for (int mt = 0; mt < 2; mt++) {
#pragma unroll
        for (int nt = 0; nt < 8; nt++) {
            const float* c = acc[mt * 8 + nt];
            int col = col0 + wc + nt * 8 + lq * 2;
            float b0 = bias[col], b1 = bias[col + 1];
            int r0 = row0 + wr + mt * 16 + lr;
            int r1 = r0 + 8;
            float2 o;
            if (r0 < n) {
                o.x = c[0] + b0; o.y = c[1] + b1;
                if (relu) { o.x = fmaxf(o.x, 0.f); o.y = fmaxf(o.y, 0.f); }
                *(float2*)&C[(size_t)r0 * ldc + col] = o;
                if (wh) Ch[(size_t)r0 * 128 + (col >> 1)] = pack_h2(o.x, o.y);
            }
            if (r1 < n) {
                o.x = c[2] + b0; o.y = c[3] + b1;
                if (relu) { o.x = fmaxf(o.x, 0.f); o.y = fmaxf(o.y, 0.f); }
                *(float2*)&C[(size_t)r1 * ldc + col] = o;
                if (wh) Ch[(size_t)r1 * 128 + (col >> 1)] = pack_h2(o.x, o.y);
            }
        }
    }
}

// ---------------- init: zero degrees + index width detection ----------------
__global__ void init_deg_kernel(const void* ei) {
    int i = blockIdx.x * blockDim.x + threadIdx.x;
    if (i < Nn) g_deg[i] = 0;
    if (i == 0) {
        const long long* p = (const long long*)ei;
        int ok = 1;
        for (int k = 0; k < 64; k++) {
            long long v = p[k];
            if (v < 0 || v >= Nn) { ok = 0; break; }
        }
        g_idx64 = ok;
    }
}

__global__ void convert_count_kernel(const void* ei) {
    int m = blockIdx.x * blockDim.x + threadIdx.x;
    if (m >= Mm) return;
    int is64 = g_idx64;
    int s, d;
    if (m < Ee) {
        if (is64) { s = (int)((const long long*)ei)[m]; d = (int)((const long long*)ei)[(long long)Ee + m]; }
        else      { s = ((const int*)ei)[m];            d = ((const int*)ei)[Ee + m]; }
    } else { s = d = m - Ee; }
    g_src[m] = s;
    g_dst[m] = d;
    atomicAdd(&g_deg[d], 1);
}

__global__ void scan1_kernel() {
    __shared__ int smi[SCANB];
    int i = blockIdx.x * SCANB + threadIdx.x;
    int v = (i < Nn) ? g_deg[i] : 0;
    smi[threadIdx.x] = v;
    __syncthreads();
    for (int o = 1; o < SCANB; o <<= 1) {
        int t = (threadIdx.x >= o) ? smi[threadIdx.x - o] : 0;
        __syncthreads();
        smi[threadIdx.x] += t;
        __syncthreads();
    }
    if (i < Nn) g_incl[i] = smi[threadIdx.x];
    if (threadIdx.x == SCANB - 1) g_bsum[blockIdx.x] = smi[SCANB - 1];
}

__global__ void scan2_kernel() {
    __shared__ int smi[64];
    int t = threadIdx.x;
    int v = (t < NSCANB) ? g_bsum[t] : 0;
    smi[t] = v;
    __syncthreads();
    for (int o = 1; o < 64; o <<= 1) {
        int u = (t >= o) ? smi[t - o] : 0;
        __syncthreads();
        smi[t] += u;
        __syncthreads();
    }
    if (t < NSCANB) g_bsum[t] = smi[t];
}

__global__ void scan3_kernel() {
    int i = blockIdx.x * blockDim.x + threadIdx.x;
    if (i >= Nn) return;
    int b = i >> 10;
    int excl = g_incl[i] - g_deg[i] + (b ? g_bsum[b - 1] : 0);
    g_rowptr[i] = excl;
    g_cursor[i] = excl;
    if (i == 0) g_rowptr[Nn] = Mm;
}

__global__ void csr_fill_kernel() {
    int m = blockIdx.x * blockDim.x + threadIdx.x;
    if (m >= Mm) return;
    int d = g_dst[m];
    int pos = atomicAdd(&g_cursor[d], 1);
    g_csrsrc[pos] = g_src[m];
}

// ---------------- fused edge phase (warp/dst) on interleaved xlr[N][512] ------------
__global__ __launch_bounds__(256)
void edge_fused_kernel(const int* __restrict__ rowptr, const int* __restrict__ csrsrc,
                       const float4* __restrict__ xlr,
                       const float4* __restrict__ att4,
                       const float4* __restrict__ bias_c4,
                       const float4* __restrict__ lg4, const float4* __restrict__ lb4,
                       float4* __restrict__ x,
                       uint32_t* __restrict__ xh32) {
    int d = (blockIdx.x * blockDim.x + threadIdx.x) >> 5;
    int lane = threadIdx.x & 31;
    if (d >= Nn) return;

    float4 r0 = xlr[(size_t)d * 128 + 64 + lane];   // xr = cols 256..511
    float4 r1 = xlr[(size_t)d * 128 + 96 + lane];
    float4 t0 = att4[lane];
    float4 t1 = att4[32 + lane];

    float m = -INFINITY, s = 0.f;
    float4 acc0 = make_float4(0,0,0,0), acc1 = make_float4(0,0,0,0);

    int p0 = rowptr[d], p1 = rowptr[d + 1];
    int p = p0;
    for (; p + 1 < p1; p += 2) {
        int sa = csrsrc[p], sb2 = csrsrc[p + 1];
        float4 c0 = xlr[(size_t)sa * 128 + lane];
        float4 c1 = xlr[(size_t)sa * 128 + 32 + lane];
        float4 d0 = xlr[(size_t)sb2 * 128 + lane];
        float4 d1 = xlr[(size_t)sb2 * 128 + 32 + lane];
        float e1 = 0.f, e2 = 0.f, v;
        v = c0.x + r0.x; v = (v > 0.f) ? v : 0.2f * v; e1 = fmaf(v, t0.x, e1);
        v = d0.x + r0.x; v = (v > 0.f) ? v : 0.2f * v; e2 = fmaf(v, t0.x, e2);
        v = c0.y + r0.y; v = (v > 0.f) ? v : 0.2f * v; e1 = fmaf(v, t0.y, e1);
        v = d0.y + r0.y; v = (v > 0.f) ? v : 0.2f * v; e2 = fmaf(v, t0.y, e2);
        v = c0.z + r0.z; v = (v > 0.f) ? v : 0.2f * v; e1 = fmaf(v, t0.z, e1);
        v = d0.z + r0.z; v = (v > 0.f) ? v : 0.2f * v; e2 = fmaf(v, t0.z, e2);
        v = c0.w + r0.w; v = (v > 0.f) ? v : 0.2f * v; e1 = fmaf(v, t0.w, e1);
        v = d0.w + r0.w; v = (v > 0.f) ? v : 0.2f * v; e2 = fmaf(v, t0.w, e2);
        v = c1.x + r1.x; v = (v > 0.f) ? v : 0.2f * v; e1 = fmaf(v, t1.x, e1);
        v = d1.x + r1.x; v = (v > 0.f) ? v : 0.2f * v; e2 = fmaf(v, t1.x, e2);
        v = c1.y + r1.y; v = (v > 0.f) ? v : 0.2f * v; e1 = fmaf(v, t1.y, e1);
        v = d1.y + r1.y; v = (v > 0.f) ? v : 0.2f * v; e2 = fmaf(v, t1.y, e2);
        v = c1.z + r1.z; v = (v > 0.f) ? v : 0.2f * v; e1 = fmaf(v, t1.z, e1);
        v = d1.z + r1.z; v = (v > 0.f) ? v : 0.2f * v; e2 = fmaf(v, t1.z, e2);
        v = c1.w + r1.w; v = (v > 0.f) ? v : 0.2f * v; e1 = fmaf(v, t1.w, e1);
        v = d1.w + r1.w; v = (v > 0.f) ? v : 0.2f * v; e2 = fmaf(v, t1.w, e2);
#pragma unroll
        for (int o = 16; o; o >>= 1) {
            e1 += __shfl_xor_sync(0xffffffffu, e1, o);
            e2 += __shfl_xor_sync(0xffffffffu, e2, o);
        }
        float mn = fmaxf(m, fmaxf(e1, e2));
        float cc = __expf(m - mn);
        float w1 = __expf(e1 - mn);
        float w2 = __expf(e2 - mn);
        s = s * cc + w1 + w2;
        acc0.x = acc0.x * cc + w1 * c0.x + w2 * d0.x;
        acc0.y = acc0.y * cc + w1 * c0.y + w2 * d0.y;
        acc0.z = acc0.z * cc + w1 * c0.z + w2 * d0.z;
        acc0.w = acc0.w * cc + w1 * c0.w + w2 * d0.w;
        acc1.x = acc1.x * cc + w1 * c1.x + w2 * d1.x;
        acc1.y = acc1.y * cc + w1 * c1.y + w2 * d1.y;
        acc1.z = acc1.z * cc + w1 * c1.z + w2 * d1.z;
        acc1.w = acc1.w * cc + w1 * c1.w + w2 * d1.w;
        m = mn;
    }
    if (p < p1) {
        int sa = csrsrc[p];
        float4 c0 = xlr[(size_t)sa * 128 + lane];
        float4 c1 = xlr[(size_t)sa * 128 + 32 + lane];
        float e = 0.f, v;
        v = c0.x + r0.x; v = (v > 0.f) ? v : 0.2f * v; e = fmaf(v, t0.x, e);
        v = c0.y + r0.y; v = (v > 0.f) ? v : 0.2f * v; e = fmaf(v, t0.y, e);
        v = c0.z + r0.z; v = (v > 0.f) ? v : 0.2f * v; e = fmaf(v, t0.z, e);
        v = c0.w + r0.w; v = (v > 0.f) ? v : 0.2f * v; e = fmaf(v, t0.w, e);
        v = c1.x + r1.x; v = (v > 0.f) ? v : 0.2f * v; e = fmaf(v, t1.x, e);
        v = c1.y + r1.y; v = (v > 0.f) ? v : 0.2f * v; e = fmaf(v, t1.y, e);
        v = c1.z + r1.z; v = (v > 0.f) ? v : 0.2f * v; e = fmaf(v, t1.z, e);
        v = c1.w + r1.w; v = (v > 0.f) ? v : 0.2f * v; e = fmaf(v, t1.w, e);
#pragma unroll
        for (int o = 16; o; o >>= 1) e += __shfl_xor_sync(0xffffffffu, e, o);
        float mn = fmaxf(m, e);
        float cc = __expf(m - mn);
        float w = __expf(e - mn);
        s = s * cc + w;
        acc0.x = acc0.x * cc + w * c0.x; acc0.y = acc0.y * cc + w * c0.y;
        acc0.z = acc0.z * cc + w * c0.z; acc0.w = acc0.w * cc + w * c0.w;
        acc1.x = acc1.x * cc + w * c1.x; acc1.y = acc1.y * cc + w * c1.y;
        acc1.z = acc1.z * cc + w * c1.z; acc1.w = acc1.w * cc + w * c1.w;
        m = mn;
    }

    float inv = 1.f / s;
    float4 bc0 = bias_c4[lane], bc1 = bias_c4[32 + lane];
    float v0x = acc0.x * inv + bc0.x, v0y = acc0.y * inv + bc0.y;
    float v0z = acc0.z * inv + bc0.z, v0w = acc0.w * inv + bc0.w;
    float v1x = acc1.x * inv + bc1.x, v1y = acc1.y * inv + bc1.y;
    float v1z = acc1.z * inv + bc1.z, v1w = acc1.w * inv + bc1.w;

    float sum = v0x + v0y + v0z + v0w + v1x + v1y + v1z + v1w;
#pragma unroll
    for (int o = 16; o; o >>= 1) sum += __shfl_xor_sync(0xffffffffu, sum, o);
    float mu = sum * (1.f / Hh);
    float d0x = v0x - mu, d0y = v0y - mu, d0z = v0z - mu, d0w = v0w - mu;
    float d1x = v1x - mu, d1y = v1y - mu, d1z = v1z - mu, d1w = v1w - mu;
    float vsum = d0x*d0x + d0y*d0y + d0z*d0z + d0w*d0w + d1x*d1x + d1y*d1y + d1z*d1z + d1w*d1w;
#pragma unroll
    for (int o = 16; o; o >>= 1) vsum += __shfl_xor_sync(0xffffffffu, vsum, o);
    float rs = rsqrtf(vsum * (1.f / Hh) + 1e-5f);

    float4 lg0 = lg4[lane], lg1 = lg4[32 + lane];
    float4 lb0 = lb4[lane], lb1 = lb4[32 + lane];
    float4 xr0 = x[(size_t)d * 64 + lane];
    float4 xr1 = x[(size_t)d * 64 + 32 + lane];
    float4 o0, o1;
    o0.x = fmaxf(d0x * rs * lg0.x + lb0.x, 0.f) + xr0.x;
    o0.y = fmaxf(d0y * rs * lg0.y + lb0.y, 0.f) + xr0.y;
    o0.z = fmaxf(d0z * rs * lg0.z + lb0.z, 0.f) + xr0.z;
    o0.w = fmaxf(d0w * rs * lg0.w + lb0.w, 0.f) + xr0.w;
    o1.x = fmaxf(d1x * rs * lg1.x + lb1.x, 0.f) + xr1.x;
    o1.y = fmaxf(d1y * rs * lg1.y + lb1.y, 0.f) + xr1.y;
    o1.z = fmaxf(d1z * rs * lg1.z + lb1.z, 0.f) + xr1.z;
    o1.w = fmaxf(d1w * rs * lg1.w + lb1.w, 0.f) + xr1.w;
    x[(size_t)d * 64 + lane] = o0;
    x[(size_t)d * 64 + 32 + lane] = o1;

    // fp16 pack for next layer's GEMM A operand
    size_t b32 = (size_t)d * 128 + 2 * lane;
    xh32[b32]      = pack_h2(o0.x, o0.y);
    xh32[b32 + 1]  = pack_h2(o0.z, o0.w);
    xh32[b32 + 64] = pack_h2(o1.x, o1.y);
    xh32[b32 + 65] = pack_h2(o1.z, o1.w);
}

// ---------------- gate dot ----------------
__global__ void gate_dot_kernel(const float4* __restrict__ hid, const float4* __restrict__ Wg2,
                                const float* __restrict__ bg2, float* __restrict__ gate) {
    int w = (blockIdx.x * blockDim.x + threadIdx.x) >> 5;
    int lane = threadIdx.x & 31;
    if (w >= Nn) return;
    const float4* p = hid + (size_t)w * 64;
    float sum = 0.f;
#pragma unroll
    for (int j = lane; j < 64; j += 32) {
        float4 a = p[j], t = Wg2[j];
        sum = fmaf(a.x, t.x, fmaf(a.y, t.y, fmaf(a.z, t.z, fmaf(a.w, t.w, sum))));
    }
#pragma unroll
    for (int o = 16; o; o >>= 1) sum += __shfl_xor_sync(0xffffffffu, sum, o);
    if (lane == 0) gate[w] = sum + bg2[0];
}

// ---------------- batch segment boundaries ----------------
__global__ void bstart_kernel(const void* __restrict__ batch) {
    int g = threadIdx.x;
    if (g > Gg) return;
    if (g == Gg) { g_bstart[Gg] = Nn; return; }
    int is64 = g_idx64;
    int lo = 0, hi = Nn;
    while (lo < hi) {
        int mid = (lo + hi) >> 1;
        long long v = is64 ? ((const long long*)batch)[mid] : (long long)((const int*)batch)[mid];
        if (v < g) lo = mid + 1; else hi = mid;
    }
    g_bstart[g] = lo;
}

// ---------------- segmented softmax pooling ----------------
__global__ __launch_bounds__(256)
void segpool_kernel(const float* __restrict__ gate, const float* __restrict__ x,
                    float* __restrict__ pooled) {
    int g = blockIdx.x, tid = threadIdx.x;
    int s = g_bstart[g], e = g_bstart[g + 1];
    __shared__ float red[8];
    __shared__ float ws[256];
    if (s >= e) { pooled[(size_t)g * Hh + tid] = 0.f; return; }

    float m = -INFINITY;
    for (int i = s + tid; i < e; i += 256) m = fmaxf(m, gate[i]);
#pragma unroll
    for (int o = 16; o; o >>= 1) m = fmaxf(m, __shfl_xor_sync(0xffffffffu, m, o));
    if ((tid & 31) == 0) red[tid >> 5] = m;
    __syncthreads();
    m = fmaxf(fmaxf(fmaxf(red[0], red[1]), fmaxf(red[2], red[3])),
              fmaxf(fmaxf(red[4], red[5]), fmaxf(red[6], red[7])));
    __syncthreads();

    float sum = 0.f;
    for (int i = s + tid; i < e; i += 256) sum += __expf(gate[i] - m);
#pragma unroll
    for (int o = 16; o; o >>= 1) sum += __shfl_xor_sync(0xffffffffu, sum, o);
    if ((tid & 31) == 0) red[tid >> 5] = sum;
    __syncthreads();
    sum = red[0] + red[1] + red[2] + red[3] + red[4] + red[5] + red[6] + red[7];
    __syncthreads();

    float acc = 0.f;
    for (int i0 = s; i0 < e; i0 += 256) {
        int n = min(256, e - i0);
        if (tid < n) ws[tid] = __expf(gate[i0 + tid] - m);
        __syncthreads();
        for (int j = 0; j < n; j++) acc = fmaf(ws[j], x[(size_t)(i0 + j) * Hh + tid], acc);
        __syncthreads();
    }
    pooled[(size_t)g * Hh + tid] = acc / sum;
}

// ---------------- head ----------------
__global__ void head_kernel(const float* __restrict__ pooled,
                            const float* __restrict__ Ws, const float* __restrict__ bs,
                            const float* __restrict__ Wc, const float* __restrict__ bc,
                            const float* __restrict__ Wr1, const float* __restrict__ br1,
                            const float* __restrict__ Wr2, const float* __restrict__ br2,
                            float* __restrict__ out) {
    int g = blockIdx.x, t = threadIdx.x;
    __shared__ float sp[Hh];
    __shared__ float sz[Hh];
    __shared__ float sr[128];
    sp[t] = pooled[(size_t)g * Hh + t];
    __syncthreads();
    float acc = bs[t];
#pragma unroll 8
    for (int k = 0; k < Hh; k++) acc = fmaf(sp[k], Ws[(size_t)t * Hh + k], acc);
    sz[t] = fmaxf(acc, 0.f);
    __syncthreads();
    if (t < NBc) {
        float a2 = bc[t];
#pragma unroll 8
        for (int k = 0; k < Hh; k++) a2 = fmaf(sz[k], Wc[(size_t)t * Hh + k], a2);
        out[(size_t)g * NBc + t] = a2;
    }
    if (t < 128) {
        float a3 = br1[t];
#pragma unroll 8
        for (int k = 0; k < Hh; k++) a3 = fmaf(sz[k], Wr1[(size_t)t * Hh + k], a3);
        sr[t] = fmaxf(a3, 0.f);
    }
    __syncthreads();
    if (t < 128) {
        float v = sr[t] * Wr2[t];
#pragma unroll
        for (int o = 16; o; o >>= 1) v += __shfl_xor_sync(0xffffffffu, v, o);
        if ((t & 31) == 0) sp[t >> 5] = v;
    }
    __syncthreads();
    if (t == 0) {
        float tot = sp[0] + sp[1] + sp[2] + sp[3] + br2[0];
        out[(size_t)Gg * NBc + g] = tanhf(tot);
    }
}

// ---------------- launch ----------------
extern "C" void kernel_launch(void* const* d_in, const int* in_sizes, int n_in,
                              void* d_out, int out_size) {
    const float* x_in   = (const float*)d_in[0];
    const void*  ei     = d_in[1];
    const void*  batch  = d_in[2];
    const float* W_in   = (const float*)d_in[3];
    const float* b_in   = (const float*)d_in[4];
    const float* Wl     = (const float*)d_in[5];
    const float* bl     = (const float*)d_in[6];
    const float* Wr     = (const float*)d_in[7];
    const float* br     = (const float*)d_in[8];
    const float* att    = (const float*)d_in[9];
    const float* bias_c = (const float*)d_in[10];
    const float* ln_g   = (const float*)d_in[11];
    const float* ln_b   = (const float*)d_in[12];
    const float* Wg1    = (const float*)d_in[13];
    const float* bg1    = (const float*)d_in[14];
    const float* Wg2    = (const float*)d_in[15];
    const float* bg2    = (const float*)d_in[16];
    const float* Ws     = (const float*)d_in[17];
    const float* bs     = (const float*)d_in[18];
    const float* Wc     = (const float*)d_in[19];
    const float* bc     = (const float*)d_in[20];
    const float* Wr1    = (const float*)d_in[21];
    const float* br1    = (const float*)d_in[22];
    const float* Wr2    = (const float*)d_in[23];
    const float* br2    = (const float*)d_in[24];
    float* out = (float*)d_out;

    float *px, *pxlr, *pxl, *pgate, *ppooled, *pbiascat;
    __half *pxh, *pxinh, *pwhi, *pwlo;
    int *prowptr, *pcsrsrc;
    cudaGetSymbolAddress((void**)&px,      g_x);
    cudaGetSymbolAddress((void**)&pxlr,    g_xlr);
    cudaGetSymbolAddress((void**)&pxl,     g_xl);
    cudaGetSymbolAddress((void**)&pxh,     g_xh);
    cudaGetSymbolAddress((void**)&pxinh,   g_xinh);
    cudaGetSymbolAddress((void**)&pwhi,    g_whi);
    cudaGetSymbolAddress((void**)&pwlo,    g_wlo);
    cudaGetSymbolAddress((void**)&pbiascat,g_biascat);
    cudaGetSymbolAddress((void**)&pgate,   g_gate);
    cudaGetSymbolAddress((void**)&ppooled, g_pooled);
    cudaGetSymbolAddress((void**)&prowptr, g_rowptr);
    cudaGetSymbolAddress((void**)&pcsrsrc, g_csrsrc);

    cudaFuncSetAttribute(gemm_fp16_kernel, cudaFuncAttributeMaxDynamicSharedMemorySize, GSM_TOT);

    const dim3 proj_grid(2, (Nn + 127) / 128);
    const dim3 fused_grid(4, (Nn + 127) / 128);
    const int NODE_W_BLOCKS = (Nn * 32 + 255) / 256;

    // ---- weight + input splits ----
    split_pairs_kernel<<<(16384/2 + 255)/256, 256>>>((const float2*)W_in,
        (uint32_t*)(pwhi + WOFF_IN), (uint32_t*)(pwlo + WOFF_IN), 16384/2);
    split_wcat_kernel<<<(Ll*512*128 + 255)/256, 256>>>((const float2*)Wl, (const float2*)Wr,
        (uint32_t*)(pwhi + WOFF_LR), (uint32_t*)(pwlo + WOFF_LR));
    split_pairs_kernel<<<(65536/2 + 255)/256, 256>>>((const float2*)Wg1,
        (uint32_t*)(pwhi + WOFF_G1), (uint32_t*)(pwlo + WOFF_G1), 65536/2);
    conv_xin_kernel<<<(NPAD*(IND/2) + 255)/256, 256>>>((const float2*)x_in, (uint32_t*)pxinh);
    biascat_kernel<<<(Ll*512 + 255)/256, 256>>>(bl, br);

    // ---- CSR build ----
    init_deg_kernel<<<(Nn + 255) / 256, 256>>>(ei);
    convert_count_kernel<<<(Mm + 255) / 256, 256>>>(ei);
    scan1_kernel<<<NSCANB, SCANB>>>();
    scan2_kernel<<<1, 64>>>();
    scan3_kernel<<<(Nn + 255) / 256, 256>>>();
    csr_fill_kernel<<<(Mm + 255) / 256, 256>>>();
    bstart_kernel<<<1, Gg + 1>>>(batch);

    // ---- input projection (K=64): fp32 out + fp16 pack for layer-0 GEMMs ----
    gemm_fp16_kernel<<<proj_grid, 256, GSM_TOT>>>(pxinh,
        pwhi + WOFF_IN, pwlo + WOFF_IN, b_in, px, Hh,
        (uint32_t*)pxh, 1, Nn, IND, 0);

    // ---- GAT layers: one fused N=512 GEMM per layer ----
    for (int l = 0; l < Ll; l++) {
        gemm_fp16_kernel<<<fused_grid, 256, GSM_TOT>>>(pxh,
            pwhi + WOFF_LR + (size_t)l * 512 * Hh, pwlo + WOFF_LR + (size_t)l * 512 * Hh,
            pbiascat + l * 512, pxlr, 512, nullptr, 0, Nn, Hh, 0);
        edge_fused_kernel<<<NODE_W_BLOCKS, 256>>>(prowptr, pcsrsrc,
            (const float4*)pxlr,
            (const float4*)(att + l * Hh),
            (const float4*)(bias_c + l * Hh),
            (const float4*)(ln_g + l * Hh), (const float4*)(ln_b + l * Hh),
            (float4*)px, (uint32_t*)pxh);
    }

    // ---- readout ----
    gemm_fp16_kernel<<<proj_grid, 256, GSM_TOT>>>(pxh,
        pwhi + WOFF_G1, pwlo + WOFF_G1, bg1, pxl, Hh, nullptr, 0, Nn, Hh, 1);
    gate_dot_kernel<<<NODE_W_BLOCKS, 256>>>((const float4*)pxl, (const float4*)Wg2, bg2, pgate);
    segpool_kernel<<<Gg, 256>>>(pgate, px, ppooled);
    head_kernel<<<Gg, Hh>>>(ppooled, Ws, bs, Wc, bc, Wr1, br1, Wr2, br2, out);
}